// round 5
// baseline (speedup 1.0000x reference)
#include <cuda_runtime.h>
#include <math.h>
#include <stdint.h>

#define SEQ 4096
#define DIM 1280
#define NH 20
#define HD 64
#define FFNDIM 5120
#define SEGLEN 512

// ---------------- scratch (no allocations allowed) ----------------
__device__ float g_xln[SEQ * DIM];
__device__ float g_q[SEQ * DIM];
__device__ float g_k[SEQ * DIM];
__device__ float g_v[SEQ * DIM];
__device__ float g_attn[SEQ * DIM];
__device__ float g_h[SEQ * DIM];
__device__ float g_yln[SEQ * DIM];
__device__ float g_mid[(size_t)SEQ * FFNDIM];
// transposed weights (K-major, [N,K])
__device__ float g_wqt[DIM * DIM];
__device__ float g_wkt[DIM * DIM];
__device__ float g_wvt[DIM * DIM];
__device__ float g_wot[DIM * DIM];
__device__ float g_wf1t[(size_t)FFNDIM * DIM];
__device__ float g_wf2t[(size_t)DIM * FFNDIM];

// ---------------- helpers ----------------
__device__ __forceinline__ uint32_t f2tf(float x) {
    uint32_t u;
    asm("cvt.rna.tf32.f32 %0, %1;" : "=r"(u) : "f"(x));
    return u;
}

__device__ __forceinline__ void mma_tf32(float* d, const uint32_t* a,
                                         const uint32_t* b) {
    asm volatile(
        "mma.sync.aligned.m16n8k8.row.col.f32.tf32.tf32.f32 "
        "{%0,%1,%2,%3}, {%4,%5,%6,%7}, {%8,%9}, {%0,%1,%2,%3};"
        : "+f"(d[0]), "+f"(d[1]), "+f"(d[2]), "+f"(d[3])
        : "r"(a[0]), "r"(a[1]), "r"(a[2]), "r"(a[3]),
          "r"(b[0]), "r"(b[1]));
}

// ---------------- transpose: out[C,R] = in[R,C]^T ----------------
__global__ void transpose_k(const float* __restrict__ in, float* __restrict__ out,
                            int R, int C) {
    __shared__ float t[32][33];
    int c = blockIdx.x * 32 + threadIdx.x;
    int r = blockIdx.y * 32 + threadIdx.y;
#pragma unroll
    for (int j = 0; j < 32; j += 8)
        t[threadIdx.y + j][threadIdx.x] = in[(size_t)(r + j) * C + c];
    __syncthreads();
    int oc = blockIdx.y * 32 + threadIdx.x;
    int orr = blockIdx.x * 32 + threadIdx.y;
#pragma unroll
    for (int j = 0; j < 32; j += 8)
        out[(size_t)(orr + j) * R + oc] = t[threadIdx.x][threadIdx.y + j];
}

// ---------------- LayerNorm ----------------
__global__ void ln_kernel(const float* __restrict__ x, const float* __restrict__ g,
                          const float* __restrict__ b, float* __restrict__ y) {
    int row = blockIdx.x;
    const float* xr = x + (size_t)row * DIM;
    float v[5];
    float s = 0.f, sq = 0.f;
#pragma unroll
    for (int i = 0; i < 5; i++) {
        v[i] = xr[threadIdx.x + i * 256];
        s += v[i];
        sq += v[i] * v[i];
    }
    __shared__ float red[64];
#pragma unroll
    for (int o = 16; o > 0; o >>= 1) {
        s += __shfl_xor_sync(0xFFFFFFFFu, s, o);
        sq += __shfl_xor_sync(0xFFFFFFFFu, sq, o);
    }
    int w = threadIdx.x >> 5, l = threadIdx.x & 31;
    if (l == 0) { red[w] = s; red[w + 8] = sq; }
    __syncthreads();
    if (threadIdx.x < 32) {
        float ss = (threadIdx.x < 8) ? red[threadIdx.x] : 0.f;
        float qq = (threadIdx.x < 8) ? red[threadIdx.x + 8] : 0.f;
#pragma unroll
        for (int o = 4; o > 0; o >>= 1) {
            ss += __shfl_xor_sync(0xFFFFFFFFu, ss, o);
            qq += __shfl_xor_sync(0xFFFFFFFFu, qq, o);
        }
        if (threadIdx.x == 0) { red[32] = ss; red[33] = qq; }
    }
    __syncthreads();
    float mu  = red[32] * (1.f / DIM);
    float var = red[33] * (1.f / DIM) - mu * mu;
    float inv = rsqrtf(var + 1e-5f);
    float* yr = y + (size_t)row * DIM;
#pragma unroll
    for (int i = 0; i < 5; i++) {
        int c = threadIdx.x + i * 256;
        yr[c] = (v[i] - mu) * inv * g[c] + b[c];
    }
}

// ---------------- tf32 mma.sync GEMM: C[M,Ntot] = A[M,K] @ Bt[N,K]^T ----------------
#define EPI_NONE 0
#define EPI_BIAS 1
#define EPI_GELU 2
#define EPI_BIAS_RES 3

#define BK 32
#define PITCH 36                  // BK + 4 pad: (36*g + c) mod 32 bijective over warp
#define TSZ (128 * PITCH)         // floats per tile buffer
#define GEMM_DSMEM (4 * TSZ * 4)  // 2 buffers x (A + B) = 73728 bytes

template <int EPI>
__global__ __launch_bounds__(256) void mma_gemm(
    const float* __restrict__ A, const float* __restrict__ Bt,
    const float* __restrict__ bias, const float* __restrict__ res,
    float* __restrict__ C, int Ntot, int K) {
    extern __shared__ float sm[];
    // layout: As0, As1, Bs0, Bs1
    float* Asb[2] = {sm, sm + TSZ};
    float* Bsb[2] = {sm + 2 * TSZ, sm + 3 * TSZ};

    int tid = threadIdx.x;
    int wid = tid >> 5, lane = tid & 31;
    int warp_m = wid & 1;          // 0..1 -> 64 rows each
    int warp_n = wid >> 1;         // 0..3 -> 32 cols each
    int g = lane >> 2, c = lane & 3;
    int br = blockIdx.y * 128, bc = blockIdx.x * 128;

    int rowq = tid >> 3;           // 0..31
    int f4 = tid & 7;              // float4 slot in a 32-float row
    const float* Abase = A + (size_t)br * K + f4 * 4;
    const float* Bbase = Bt + (size_t)bc * K + f4 * 4;

    float acc[4][4][4];
#pragma unroll
    for (int i = 0; i < 4; i++)
#pragma unroll
        for (int j = 0; j < 4; j++)
#pragma unroll
            for (int u = 0; u < 4; u++) acc[i][j][u] = 0.f;

    const int NIT = K / BK;

    float4 av[4], bv[4];
    // load tile 0
#pragma unroll
    for (int p = 0; p < 4; p++) {
        int row = p * 32 + rowq;
        av[p] = *(const float4*)(Abase + (size_t)row * K);
        bv[p] = *(const float4*)(Bbase + (size_t)row * K);
    }
#pragma unroll
    for (int p = 0; p < 4; p++) {
        int row = p * 32 + rowq;
        uint4 ta = make_uint4(f2tf(av[p].x), f2tf(av[p].y), f2tf(av[p].z), f2tf(av[p].w));
        uint4 tb = make_uint4(f2tf(bv[p].x), f2tf(bv[p].y), f2tf(bv[p].z), f2tf(bv[p].w));
        *(uint4*)&Asb[0][row * PITCH + f4 * 4] = ta;
        *(uint4*)&Bsb[0][row * PITCH + f4 * 4] = tb;
    }
    __syncthreads();

    for (int it = 0; it < NIT; it++) {
        int cur = it & 1;
        bool more = (it + 1) < NIT;
        if (more) {
            int k0 = (it + 1) * BK;
#pragma unroll
            for (int p = 0; p < 4; p++) {
                int row = p * 32 + rowq;
                av[p] = *(const float4*)(Abase + (size_t)row * K + k0);
                bv[p] = *(const float4*)(Bbase + (size_t)row * K + k0);
            }
        }
        const uint32_t* As = (const uint32_t*)Asb[cur];
        const uint32_t* Bs = (const uint32_t*)Bsb[cur];
#pragma unroll
        for (int ks = 0; ks < 4; ks++) {
            int k0 = ks * 8;
            uint32_t af[4][4], bf[4][2];
#pragma unroll
            for (int mt = 0; mt < 4; mt++) {
                int rm = warp_m * 64 + mt * 16 + g;
                af[mt][0] = As[rm * PITCH + k0 + c];
                af[mt][1] = As[(rm + 8) * PITCH + k0 + c];
                af[mt][2] = As[rm * PITCH + k0 + c + 4];
                af[mt][3] = As[(rm + 8) * PITCH + k0 + c + 4];
            }
#pragma unroll
            for (int nt = 0; nt < 4; nt++) {
                int rn = warp_n * 32 + nt * 8 + g;
                bf[nt][0] = Bs[rn * PITCH + k0 + c];
                bf[nt][1] = Bs[rn * PITCH + k0 + c + 4];
            }
#pragma unroll
            for (int mt = 0; mt < 4; mt++)
#pragma unroll
                for (int nt = 0; nt < 4; nt++)
                    mma_tf32(acc[mt][nt], af[mt], bf[nt]);
        }
        if (more) {
            int nxt = cur ^ 1;
#pragma unroll
            for (int p = 0; p < 4; p++) {
                int row = p * 32 + rowq;
                uint4 ta = make_uint4(f2tf(av[p].x), f2tf(av[p].y), f2tf(av[p].z), f2tf(av[p].w));
                uint4 tb = make_uint4(f2tf(bv[p].x), f2tf(bv[p].y), f2tf(bv[p].z), f2tf(bv[p].w));
                *(uint4*)&Asb[nxt][row * PITCH + f4 * 4] = ta;
                *(uint4*)&Bsb[nxt][row * PITCH + f4 * 4] = tb;
            }
        }
        __syncthreads();
    }

    // epilogue
#pragma unroll
    for (int mt = 0; mt < 4; mt++) {
#pragma unroll
        for (int nt = 0; nt < 4; nt++) {
            int col = bc + warp_n * 32 + nt * 8 + c * 2;
#pragma unroll
            for (int half = 0; half < 2; half++) {
                int row = br + warp_m * 64 + mt * 16 + g + half * 8;
                float x0 = acc[mt][nt][half * 2 + 0];
                float x1 = acc[mt][nt][half * 2 + 1];
                if (EPI == EPI_BIAS || EPI == EPI_GELU || EPI == EPI_BIAS_RES) {
                    x0 += bias[col];
                    x1 += bias[col + 1];
                }
                if (EPI == EPI_GELU) {
                    x0 = 0.5f * x0 * (1.f + erff(x0 * 0.70710678118654752f));
                    x1 = 0.5f * x1 * (1.f + erff(x1 * 0.70710678118654752f));
                }
                if (EPI == EPI_BIAS_RES) {
                    float2 r2 = *(const float2*)(res + (size_t)row * Ntot + col);
                    x0 += r2.x;
                    x1 += r2.y;
                }
                *(float2*)(C + (size_t)row * Ntot + col) = make_float2(x0, x1);
            }
        }
    }
}

// ---------------- block-diagonal attention (fp32, unchanged) ----------------
#define SCORE_PITCH 33
#define QS_OFF (512 * SCORE_PITCH)
#define KV_OFF (QS_OFF + 32 * 65)
#define ATTN_SMEM_FLOATS (KV_OFF + 64 * 65)

__global__ __launch_bounds__(256) void attn_kernel(
    const float* __restrict__ Q, const float* __restrict__ Kg,
    const float* __restrict__ V, float* __restrict__ O) {
    extern __shared__ float sm[];
    float* scoresT = sm;
    float* Qs = sm + QS_OFF;
    float* KVs = sm + KV_OFF;

    int tid = threadIdx.x;
    int qt = blockIdx.x;
    int hh = blockIdx.y;
    int sg = blockIdx.z;
    int qbase = sg * SEGLEN + qt * 32;
    int kbase = sg * SEGLEN;
    int colbase = hh * HD;

#pragma unroll
    for (int i = 0; i < 8; i++) {
        int e = tid + i * 256;
        int q = e >> 6, d = e & 63;
        Qs[q * 65 + d] = Q[(size_t)(qbase + q) * DIM + colbase + d] * 0.125f;
    }
    int ql = tid & 31;
    int grp = tid >> 5;

    for (int kt = 0; kt < 8; kt++) {
        __syncthreads();
#pragma unroll
        for (int i = 0; i < 16; i++) {
            int e = tid + i * 256;
            int k = e >> 6, d = e & 63;
            KVs[k * 65 + d] = Kg[(size_t)(kbase + kt * 64 + k) * DIM + colbase + d];
        }
        __syncthreads();
        float acc[8] = {};
#pragma unroll
        for (int d = 0; d < 64; d++) {
            float qv = Qs[ql * 65 + d];
#pragma unroll
            for (int j = 0; j < 8; j++)
                acc[j] += qv * KVs[(grp * 8 + j) * 65 + d];
        }
#pragma unroll
        for (int j = 0; j < 8; j++)
            scoresT[(kt * 64 + grp * 8 + j) * SCORE_PITCH + ql] = acc[j];
    }
    __syncthreads();

    {
        int w = tid >> 5, l = tid & 31;
        for (int qi = 0; qi < 4; qi++) {
            int q = w + qi * 8;
            float vals[16];
            float m = -1e30f;
#pragma unroll
            for (int s = 0; s < 16; s++) {
                vals[s] = scoresT[(l + s * 32) * SCORE_PITCH + q];
                m = fmaxf(m, vals[s]);
            }
#pragma unroll
            for (int o = 16; o > 0; o >>= 1) m = fmaxf(m, __shfl_xor_sync(0xFFFFFFFFu, m, o));
            float sum = 0.f;
#pragma unroll
            for (int s = 0; s < 16; s++) {
                float e = __expf(vals[s] - m);
                vals[s] = e;
                sum += e;
            }
#pragma unroll
            for (int o = 16; o > 0; o >>= 1) sum += __shfl_xor_sync(0xFFFFFFFFu, sum, o);
            float r = 1.f / sum;
#pragma unroll
            for (int s = 0; s < 16; s++)
                scoresT[(l + s * 32) * SCORE_PITCH + q] = vals[s] * r;
        }
    }

    float o[8] = {};
    for (int vt = 0; vt < 8; vt++) {
        __syncthreads();
#pragma unroll
        for (int i = 0; i < 16; i++) {
            int e = tid + i * 256;
            int k = e >> 6, d = e & 63;
            KVs[k * 65 + d] = V[(size_t)(kbase + vt * 64 + k) * DIM + colbase + d];
        }
        __syncthreads();
#pragma unroll
        for (int kk = 0; kk < 64; kk++) {
            float p = scoresT[(vt * 64 + kk) * SCORE_PITCH + ql];
#pragma unroll
            for (int j = 0; j < 8; j++)
                o[j] += p * KVs[kk * 65 + grp * 8 + j];
        }
    }

    float4* dst = (float4*)&O[(size_t)(qbase + ql) * DIM + colbase + grp * 8];
    dst[0] = make_float4(o[0], o[1], o[2], o[3]);
    dst[1] = make_float4(o[4], o[5], o[6], o[7]);
}

// ---------------- launch ----------------
extern "C" void kernel_launch(void* const* d_in, const int* in_sizes, int n_in,
                              void* d_out, int out_size) {
    const float* hidden = (const float*)d_in[0];
    const float* Wq = (const float*)d_in[2];
    const float* bq = (const float*)d_in[3];
    const float* Wk = (const float*)d_in[4];
    const float* Wv = (const float*)d_in[5];
    const float* bv = (const float*)d_in[6];
    const float* Wo = (const float*)d_in[7];
    const float* bo = (const float*)d_in[8];
    const float* g1 = (const float*)d_in[9];
    const float* b1 = (const float*)d_in[10];
    const float* Wf1 = (const float*)d_in[11];
    const float* bf1 = (const float*)d_in[12];
    const float* Wf2 = (const float*)d_in[13];
    const float* bf2 = (const float*)d_in[14];
    const float* g2 = (const float*)d_in[15];
    const float* b2 = (const float*)d_in[16];
    float* out = (float*)d_out;

    float *xln, *q, *k, *v, *attn, *h, *yln, *mid;
    float *wqt, *wkt, *wvt, *wot, *wf1t, *wf2t;
    cudaGetSymbolAddress((void**)&xln, g_xln);
    cudaGetSymbolAddress((void**)&q, g_q);
    cudaGetSymbolAddress((void**)&k, g_k);
    cudaGetSymbolAddress((void**)&v, g_v);
    cudaGetSymbolAddress((void**)&attn, g_attn);
    cudaGetSymbolAddress((void**)&h, g_h);
    cudaGetSymbolAddress((void**)&yln, g_yln);
    cudaGetSymbolAddress((void**)&mid, g_mid);
    cudaGetSymbolAddress((void**)&wqt, g_wqt);
    cudaGetSymbolAddress((void**)&wkt, g_wkt);
    cudaGetSymbolAddress((void**)&wvt, g_wvt);
    cudaGetSymbolAddress((void**)&wot, g_wot);
    cudaGetSymbolAddress((void**)&wf1t, g_wf1t);
    cudaGetSymbolAddress((void**)&wf2t, g_wf2t);

    const int ATTN_SMEM = ATTN_SMEM_FLOATS * 4;
    cudaFuncSetAttribute(attn_kernel, cudaFuncAttributeMaxDynamicSharedMemorySize, ATTN_SMEM);
    cudaFuncSetAttribute(mma_gemm<EPI_NONE>, cudaFuncAttributeMaxDynamicSharedMemorySize, GEMM_DSMEM);
    cudaFuncSetAttribute(mma_gemm<EPI_BIAS>, cudaFuncAttributeMaxDynamicSharedMemorySize, GEMM_DSMEM);
    cudaFuncSetAttribute(mma_gemm<EPI_GELU>, cudaFuncAttributeMaxDynamicSharedMemorySize, GEMM_DSMEM);
    cudaFuncSetAttribute(mma_gemm<EPI_BIAS_RES>, cudaFuncAttributeMaxDynamicSharedMemorySize, GEMM_DSMEM);

    dim3 tb(32, 8);
    // weight transposes ([R,C] -> [C,R]) so every GEMM B operand is K-major
    transpose_k<<<dim3(DIM / 32, DIM / 32), tb>>>(Wq, wqt, DIM, DIM);
    transpose_k<<<dim3(DIM / 32, DIM / 32), tb>>>(Wk, wkt, DIM, DIM);
    transpose_k<<<dim3(DIM / 32, DIM / 32), tb>>>(Wv, wvt, DIM, DIM);
    transpose_k<<<dim3(FFNDIM / 32, DIM / 32), tb>>>(Wf1, wf1t, DIM, FFNDIM);
    transpose_k<<<dim3(DIM / 32, DIM / 32), tb>>>(Wo, wot, DIM, DIM);
    transpose_k<<<dim3(DIM / 32, FFNDIM / 32), tb>>>(Wf2, wf2t, FFNDIM, DIM);

    dim3 gD(DIM / 128, SEQ / 128);
    dim3 gF(FFNDIM / 128, SEQ / 128);

    // LN1
    ln_kernel<<<SEQ, 256>>>(hidden, g1, b1, xln);
    // QKV (tf32 tensor core)
    mma_gemm<EPI_BIAS><<<gD, 256, GEMM_DSMEM>>>(xln, wqt, bq, nullptr, q, DIM, DIM);
    mma_gemm<EPI_NONE><<<gD, 256, GEMM_DSMEM>>>(xln, wkt, nullptr, nullptr, k, DIM, DIM);
    mma_gemm<EPI_BIAS><<<gD, 256, GEMM_DSMEM>>>(xln, wvt, bv, nullptr, v, DIM, DIM);
    // attention (block-diagonal, 512-token segments)
    attn_kernel<<<dim3(16, NH, 8), 256, ATTN_SMEM>>>(q, k, v, attn);
    // O proj + residual
    mma_gemm<EPI_BIAS_RES><<<gD, 256, GEMM_DSMEM>>>(attn, wot, bo, hidden, h, DIM, DIM);
    // LN2
    ln_kernel<<<SEQ, 256>>>(h, g2, b2, yln);
    // FFN
    mma_gemm<EPI_GELU><<<gF, 256, GEMM_DSMEM>>>(yln, wf1t, bf1, nullptr, mid, FFNDIM, DIM);
    mma_gemm<EPI_BIAS_RES><<<gD, 256, GEMM_DSMEM>>>(mid, wf2t, bf2, h, out, DIM, FFNDIM);
}

// round 7
// speedup vs baseline: 1.4274x; 1.4274x over previous
#include <cuda_runtime.h>
#include <math.h>
#include <stdint.h>

#define SEQ 4096
#define DIM 1280
#define NH 20
#define HD 64
#define FFNDIM 5120
#define SEGLEN 512
#define QKVN 3840

// ---------------- scratch (no allocations allowed) ----------------
__device__ float g_xln[SEQ * DIM];
__device__ float g_qkv[(size_t)SEQ * QKVN];
__device__ float g_attn[SEQ * DIM];
__device__ float g_h[SEQ * DIM];
__device__ float g_yln[SEQ * DIM];
__device__ float g_mid[(size_t)SEQ * FFNDIM];
// transposed weights (K-major, [N,K]) — QKV fused
__device__ float g_wqkvt[(size_t)QKVN * DIM];
__device__ float g_bqkv[QKVN];
__device__ float g_wot[DIM * DIM];
__device__ float g_wf1t[(size_t)FFNDIM * DIM];
__device__ float g_wf2t[(size_t)DIM * FFNDIM];

// ---------------- helpers ----------------
__device__ __forceinline__ float f2tf_f(float x) {
    uint32_t u;
    asm("cvt.rna.tf32.f32 %0, %1;" : "=r"(u) : "f"(x));
    return __uint_as_float(u);
}

__device__ __forceinline__ void mma_tf32(float* d, const uint32_t* a,
                                         const uint32_t* b) {
    asm volatile(
        "mma.sync.aligned.m16n8k8.row.col.f32.tf32.tf32.f32 "
        "{%0,%1,%2,%3}, {%4,%5,%6,%7}, {%8,%9}, {%0,%1,%2,%3};"
        : "+f"(d[0]), "+f"(d[1]), "+f"(d[2]), "+f"(d[3])
        : "r"(a[0]), "r"(a[1]), "r"(a[2]), "r"(a[3]),
          "r"(b[0]), "r"(b[1]));
}

__device__ __forceinline__ uint32_t smem_u32(const void* p) {
    uint32_t a;
    asm("{ .reg .u64 t; cvta.to.shared.u64 t, %1; cvt.u32.u64 %0, t; }" : "=r"(a) : "l"(p));
    return a;
}
#define CP_ASYNC16(s, g) \
    asm volatile("cp.async.cg.shared.global [%0], [%1], 16;" :: "r"(s), "l"(g))
#define CP_COMMIT() asm volatile("cp.async.commit_group;" ::: "memory")
#define CP_WAIT1() asm volatile("cp.async.wait_group 1;" ::: "memory")

// ---------------- transpose (rounds to tf32): out[C,R] = tf32(in[R,C]^T) ----------------
__global__ void transpose_k(const float* __restrict__ in, float* __restrict__ out,
                            int R, int C, int ldo) {
    __shared__ float t[32][33];
    int c = blockIdx.x * 32 + threadIdx.x;
    int r = blockIdx.y * 32 + threadIdx.y;
#pragma unroll
    for (int j = 0; j < 32; j += 8)
        t[threadIdx.y + j][threadIdx.x] = in[(size_t)(r + j) * C + c];
    __syncthreads();
    int oc = blockIdx.y * 32 + threadIdx.x;
    int orr = blockIdx.x * 32 + threadIdx.y;
#pragma unroll
    for (int j = 0; j < 32; j += 8)
        out[(size_t)(orr + j) * ldo + oc] = f2tf_f(t[threadIdx.x][threadIdx.y + j]);
}

// ---------------- fused QKV bias: [bq | 0 | bv] ----------------
__global__ void qkvbias_k(const float* __restrict__ bq, const float* __restrict__ bv,
                          float* __restrict__ out) {
    int i = blockIdx.x * 256 + threadIdx.x;
    float v = 0.f;
    if (i < DIM) v = bq[i];
    else if (i >= 2 * DIM) v = bv[i - 2 * DIM];
    out[i] = v;
}

// ---------------- LayerNorm (output rounded to tf32) ----------------
__global__ void ln_kernel(const float* __restrict__ x, const float* __restrict__ g,
                          const float* __restrict__ b, float* __restrict__ y) {
    int row = blockIdx.x;
    const float* xr = x + (size_t)row * DIM;
    float v[5];
    float s = 0.f, sq = 0.f;
#pragma unroll
    for (int i = 0; i < 5; i++) {
        v[i] = xr[threadIdx.x + i * 256];
        s += v[i];
        sq += v[i] * v[i];
    }
    __shared__ float red[64];
#pragma unroll
    for (int o = 16; o > 0; o >>= 1) {
        s += __shfl_xor_sync(0xFFFFFFFFu, s, o);
        sq += __shfl_xor_sync(0xFFFFFFFFu, sq, o);
    }
    int w = threadIdx.x >> 5, l = threadIdx.x & 31;
    if (l == 0) { red[w] = s; red[w + 8] = sq; }
    __syncthreads();
    if (threadIdx.x < 32) {
        float ss = (threadIdx.x < 8) ? red[threadIdx.x] : 0.f;
        float qq = (threadIdx.x < 8) ? red[threadIdx.x + 8] : 0.f;
#pragma unroll
        for (int o = 4; o > 0; o >>= 1) {
            ss += __shfl_xor_sync(0xFFFFFFFFu, ss, o);
            qq += __shfl_xor_sync(0xFFFFFFFFu, qq, o);
        }
        if (threadIdx.x == 0) { red[32] = ss; red[33] = qq; }
    }
    __syncthreads();
    float mu  = red[32] * (1.f / DIM);
    float var = red[33] * (1.f / DIM) - mu * mu;
    float inv = rsqrtf(var + 1e-5f);
    float* yr = y + (size_t)row * DIM;
#pragma unroll
    for (int i = 0; i < 5; i++) {
        int c = threadIdx.x + i * 256;
        yr[c] = f2tf_f((v[i] - mu) * inv * g[c] + b[c]);
    }
}

// ---------------- tf32 mma.sync GEMM, cp.async 3-stage ----------------
// Operands MUST already be tf32-rounded fp32 in gmem.
#define EPI_NONE 0
#define EPI_BIAS 1
#define EPI_GELU 2
#define EPI_BIAS_RES 3

#define BK 32
#define PITCH 36
#define A_FLOATS (128 * PITCH)               // 4608
#define STAGE_FLOATS (2 * A_FLOATS)          // A + B
#define GEMM_DSMEM (3 * STAGE_FLOATS * 4)    // 110592 bytes

template <int EPI>
__global__ __launch_bounds__(256) void mma_gemm(
    const float* __restrict__ A, const float* __restrict__ Bt,
    const float* __restrict__ bias, const float* __restrict__ res,
    float* __restrict__ C, int Ntot, int K) {
    extern __shared__ float sm[];
    uint32_t smb = smem_u32(sm);

    int tid = threadIdx.x;
    int wid = tid >> 5, lane = tid & 31;
    int warp_m = wid & 1;
    int warp_n = wid >> 1;
    int g = lane >> 2, c = lane & 3;
    int br = blockIdx.y * 128, bc = blockIdx.x * 128;

    int rowq = tid >> 3;           // 0..31
    int f4 = tid & 7;              // 16B slot within 32-float row
    const float* Abase = A + (size_t)br * K + f4 * 4;
    const float* Bbase = Bt + (size_t)bc * K + f4 * 4;

    const int NIT = K / BK;

    float acc[4][4][4];
#pragma unroll
    for (int i = 0; i < 4; i++)
#pragma unroll
        for (int j = 0; j < 4; j++)
#pragma unroll
            for (int u = 0; u < 4; u++) acc[i][j][u] = 0.f;

    // stage issue: 4 x 16B for A and B each
#define ISSUE_STAGE(st)                                                      \
    do {                                                                     \
        int _k0 = (st) * BK;                                                 \
        uint32_t _sa = smb + ((st) % 3) * (STAGE_FLOATS * 4);                \
        uint32_t _sb = _sa + A_FLOATS * 4;                                   \
        _Pragma("unroll")                                                    \
        for (int _p = 0; _p < 4; _p++) {                                     \
            int _row = _p * 32 + rowq;                                       \
            uint32_t _so = (uint32_t)(_row * PITCH + f4 * 4) * 4;            \
            CP_ASYNC16(_sa + _so, Abase + (size_t)_row * K + _k0);           \
            CP_ASYNC16(_sb + _so, Bbase + (size_t)_row * K + _k0);           \
        }                                                                    \
    } while (0)

    ISSUE_STAGE(0);
    CP_COMMIT();
    ISSUE_STAGE(1);
    CP_COMMIT();

    for (int it = 0; it < NIT; it++) {
        CP_WAIT1();
        __syncthreads();
        if (it + 2 < NIT) ISSUE_STAGE(it + 2);
        CP_COMMIT();

        const uint32_t* As = (const uint32_t*)(sm + (it % 3) * STAGE_FLOATS);
        const uint32_t* Bs = As + A_FLOATS;
#pragma unroll
        for (int ks = 0; ks < 4; ks++) {
            int k0 = ks * 8;
            uint32_t af[4][4], bf[4][2];
#pragma unroll
            for (int mt = 0; mt < 4; mt++) {
                int rm = warp_m * 64 + mt * 16 + g;
                af[mt][0] = As[rm * PITCH + k0 + c];
                af[mt][1] = As[(rm + 8) * PITCH + k0 + c];
                af[mt][2] = As[rm * PITCH + k0 + c + 4];
                af[mt][3] = As[(rm + 8) * PITCH + k0 + c + 4];
            }
#pragma unroll
            for (int nt = 0; nt < 4; nt++) {
                int rn = warp_n * 32 + nt * 8 + g;
                bf[nt][0] = Bs[rn * PITCH + k0 + c];
                bf[nt][1] = Bs[rn * PITCH + k0 + c + 4];
            }
#pragma unroll
            for (int mt = 0; mt < 4; mt++)
#pragma unroll
                for (int nt = 0; nt < 4; nt++)
                    mma_tf32(acc[mt][nt], af[mt], bf[nt]);
        }
        __syncthreads();
    }

    // epilogue
#pragma unroll
    for (int mt = 0; mt < 4; mt++) {
#pragma unroll
        for (int nt = 0; nt < 4; nt++) {
            int col = bc + warp_n * 32 + nt * 8 + c * 2;
#pragma unroll
            for (int half = 0; half < 2; half++) {
                int row = br + warp_m * 64 + mt * 16 + g + half * 8;
                float x0 = acc[mt][nt][half * 2 + 0];
                float x1 = acc[mt][nt][half * 2 + 1];
                if (EPI == EPI_BIAS || EPI == EPI_GELU || EPI == EPI_BIAS_RES) {
                    x0 += bias[col];
                    x1 += bias[col + 1];
                }
                if (EPI == EPI_GELU) {
                    x0 = f2tf_f(0.5f * x0 * (1.f + erff(x0 * 0.70710678118654752f)));
                    x1 = f2tf_f(0.5f * x1 * (1.f + erff(x1 * 0.70710678118654752f)));
                }
                if (EPI == EPI_BIAS_RES) {
                    float2 r2 = *(const float2*)(res + (size_t)row * Ntot + col);
                    x0 += r2.x;
                    x1 += r2.y;
                }
                *(float2*)(C + (size_t)row * Ntot + col) = make_float2(x0, x1);
            }
        }
    }
}

// ---------------- block-diagonal attention (fp32, strided QKV) ----------------
#define SCORE_PITCH 33
#define QS_OFF (512 * SCORE_PITCH)
#define KV_OFF (QS_OFF + 32 * 65)
#define ATTN_SMEM_FLOATS (KV_OFF + 64 * 65)

__global__ __launch_bounds__(256) void attn_kernel(
    const float* __restrict__ Q, const float* __restrict__ Kg,
    const float* __restrict__ V, float* __restrict__ O, int ldq) {
    extern __shared__ float sm[];
    float* scoresT = sm;
    float* Qs = sm + QS_OFF;
    float* KVs = sm + KV_OFF;

    int tid = threadIdx.x;
    int qt = blockIdx.x;
    int hh = blockIdx.y;
    int sg = blockIdx.z;
    int qbase = sg * SEGLEN + qt * 32;
    int kbase = sg * SEGLEN;
    int colbase = hh * HD;

#pragma unroll
    for (int i = 0; i < 8; i++) {
        int e = tid + i * 256;
        int q = e >> 6, d = e & 63;
        Qs[q * 65 + d] = Q[(size_t)(qbase + q) * ldq + colbase + d] * 0.125f;
    }
    int ql = tid & 31;
    int grp = tid >> 5;

    for (int kt = 0; kt < 8; kt++) {
        __syncthreads();
#pragma unroll
        for (int i = 0; i < 16; i++) {
            int e = tid + i * 256;
            int k = e >> 6, d = e & 63;
            KVs[k * 65 + d] = Kg[(size_t)(kbase + kt * 64 + k) * ldq + colbase + d];
        }
        __syncthreads();
        float acc[8] = {};
#pragma unroll
        for (int d = 0; d < 64; d++) {
            float qv = Qs[ql * 65 + d];
#pragma unroll
            for (int j = 0; j < 8; j++)
                acc[j] += qv * KVs[(grp * 8 + j) * 65 + d];
        }
#pragma unroll
        for (int j = 0; j < 8; j++)
            scoresT[(kt * 64 + grp * 8 + j) * SCORE_PITCH + ql] = acc[j];
    }
    __syncthreads();

    {
        int w = tid >> 5, l = tid & 31;
        for (int qi = 0; qi < 4; qi++) {
            int q = w + qi * 8;
            float vals[16];
            float m = -1e30f;
#pragma unroll
            for (int s = 0; s < 16; s++) {
                vals[s] = scoresT[(l + s * 32) * SCORE_PITCH + q];
                m = fmaxf(m, vals[s]);
            }
#pragma unroll
            for (int o = 16; o > 0; o >>= 1) m = fmaxf(m, __shfl_xor_sync(0xFFFFFFFFu, m, o));
            float sum = 0.f;
#pragma unroll
            for (int s = 0; s < 16; s++) {
                float e = __expf(vals[s] - m);
                vals[s] = e;
                sum += e;
            }
#pragma unroll
            for (int o = 16; o > 0; o >>= 1) sum += __shfl_xor_sync(0xFFFFFFFFu, sum, o);
            float r = 1.f / sum;
#pragma unroll
            for (int s = 0; s < 16; s++)
                scoresT[(l + s * 32) * SCORE_PITCH + q] = vals[s] * r;
        }
    }

    float o[8] = {};
    for (int vt = 0; vt < 8; vt++) {
        __syncthreads();
#pragma unroll
        for (int i = 0; i < 16; i++) {
            int e = tid + i * 256;
            int k = e >> 6, d = e & 63;
            KVs[k * 65 + d] = V[(size_t)(kbase + vt * 64 + k) * ldq + colbase + d];
        }
        __syncthreads();
#pragma unroll
        for (int kk = 0; kk < 64; kk++) {
            float p = scoresT[(vt * 64 + kk) * SCORE_PITCH + ql];
#pragma unroll
            for (int j = 0; j < 8; j++)
                o[j] += p * KVs[kk * 65 + grp * 8 + j];
        }
    }

    // output rounded to tf32 (feeds the O-projection GEMM)
    float4* dst = (float4*)&O[(size_t)(qbase + ql) * DIM + colbase + grp * 8];
    dst[0] = make_float4(f2tf_f(o[0]), f2tf_f(o[1]), f2tf_f(o[2]), f2tf_f(o[3]));
    dst[1] = make_float4(f2tf_f(o[4]), f2tf_f(o[5]), f2tf_f(o[6]), f2tf_f(o[7]));
}

// ---------------- launch ----------------
extern "C" void kernel_launch(void* const* d_in, const int* in_sizes, int n_in,
                              void* d_out, int out_size) {
    const float* hidden = (const float*)d_in[0];
    const float* Wq = (const float*)d_in[2];
    const float* bq = (const float*)d_in[3];
    const float* Wk = (const float*)d_in[4];
    const float* Wv = (const float*)d_in[5];
    const float* bv = (const float*)d_in[6];
    const float* Wo = (const float*)d_in[7];
    const float* bo = (const float*)d_in[8];
    const float* g1 = (const float*)d_in[9];
    const float* b1 = (const float*)d_in[10];
    const float* Wf1 = (const float*)d_in[11];
    const float* bf1 = (const float*)d_in[12];
    const float* Wf2 = (const float*)d_in[13];
    const float* bf2 = (const float*)d_in[14];
    const float* g2 = (const float*)d_in[15];
    const float* b2 = (const float*)d_in[16];
    float* out = (float*)d_out;

    float *xln, *qkv, *attn, *h, *yln, *mid;
    float *wqkvt, *bqkv, *wot, *wf1t, *wf2t;
    cudaGetSymbolAddress((void**)&xln, g_xln);
    cudaGetSymbolAddress((void**)&qkv, g_qkv);
    cudaGetSymbolAddress((void**)&attn, g_attn);
    cudaGetSymbolAddress((void**)&h, g_h);
    cudaGetSymbolAddress((void**)&yln, g_yln);
    cudaGetSymbolAddress((void**)&mid, g_mid);
    cudaGetSymbolAddress((void**)&wqkvt, g_wqkvt);
    cudaGetSymbolAddress((void**)&bqkv, g_bqkv);
    cudaGetSymbolAddress((void**)&wot, g_wot);
    cudaGetSymbolAddress((void**)&wf1t, g_wf1t);
    cudaGetSymbolAddress((void**)&wf2t, g_wf2t);

    const int ATTN_SMEM = ATTN_SMEM_FLOATS * 4;
    cudaFuncSetAttribute(attn_kernel, cudaFuncAttributeMaxDynamicSharedMemorySize, ATTN_SMEM);
    cudaFuncSetAttribute(mma_gemm<EPI_NONE>, cudaFuncAttributeMaxDynamicSharedMemorySize, GEMM_DSMEM);
    cudaFuncSetAttribute(mma_gemm<EPI_BIAS>, cudaFuncAttributeMaxDynamicSharedMemorySize, GEMM_DSMEM);
    cudaFuncSetAttribute(mma_gemm<EPI_GELU>, cudaFuncAttributeMaxDynamicSharedMemorySize, GEMM_DSMEM);
    cudaFuncSetAttribute(mma_gemm<EPI_BIAS_RES>, cudaFuncAttributeMaxDynamicSharedMemorySize, GEMM_DSMEM);

    dim3 tb(32, 8);
    // Wq/Wk/Wv -> fused [3840,1280] K-major (rows: q 0..1279, k 1280..2559, v 2560..3839)
    transpose_k<<<dim3(DIM / 32, DIM / 32), tb>>>(Wq, wqkvt, DIM, DIM, DIM);
    transpose_k<<<dim3(DIM / 32, DIM / 32), tb>>>(Wk, wqkvt + (size_t)DIM * DIM, DIM, DIM, DIM);
    transpose_k<<<dim3(DIM / 32, DIM / 32), tb>>>(Wv, wqkvt + (size_t)2 * DIM * DIM, DIM, DIM, DIM);
    transpose_k<<<dim3(DIM / 32, DIM / 32), tb>>>(Wo, wot, DIM, DIM, DIM);
    transpose_k<<<dim3(FFNDIM / 32, DIM / 32), tb>>>(Wf1, wf1t, DIM, FFNDIM, DIM);
    transpose_k<<<dim3(DIM / 32, FFNDIM / 32), tb>>>(Wf2, wf2t, FFNDIM, DIM, FFNDIM);
    qkvbias_k<<<QKVN / 256, 256>>>(bq, bv, bqkv);

    dim3 gQKV(QKVN / 128, SEQ / 128);
    dim3 gD(DIM / 128, SEQ / 128);
    dim3 gF(FFNDIM / 128, SEQ / 128);

    // LN1
    ln_kernel<<<SEQ, 256>>>(hidden, g1, b1, xln);
    // fused QKV GEMM -> [4096, 3840]
    mma_gemm<EPI_BIAS><<<gQKV, 256, GEMM_DSMEM>>>(xln, wqkvt, bqkv, nullptr, qkv, QKVN, DIM);
    // attention (block-diagonal, 512-token segments), strided into fused qkv
    attn_kernel<<<dim3(16, NH, 8), 256, ATTN_SMEM>>>(qkv, qkv + DIM, qkv + 2 * DIM, attn, QKVN);
    // O proj + residual
    mma_gemm<EPI_BIAS_RES><<<gD, 256, GEMM_DSMEM>>>(attn, wot, bo, hidden, h, DIM, DIM);
    // LN2
    ln_kernel<<<SEQ, 256>>>(h, g2, b2, yln);
    // FFN
    mma_gemm<EPI_GELU><<<gF, 256, GEMM_DSMEM>>>(yln, wf1t, bf1, nullptr, mid, FFNDIM, DIM);
    mma_gemm<EPI_BIAS_RES><<<gD, 256, GEMM_DSMEM>>>(mid, wf2t, bf2, h, out, DIM, FFNDIM);
}

// round 8
// speedup vs baseline: 1.5925x; 1.1157x over previous
#include <cuda_runtime.h>
#include <math.h>
#include <stdint.h>

#define SEQ 4096
#define DIM 1280
#define NH 20
#define HD 64
#define FFNDIM 5120
#define SEGLEN 512
#define QKVN 3840

// ---------------- scratch (no allocations allowed) ----------------
__device__ float g_xln[SEQ * DIM];
__device__ float g_qkv[(size_t)SEQ * QKVN];
__device__ float g_attn[SEQ * DIM];
__device__ float g_h[SEQ * DIM];
__device__ float g_yln[SEQ * DIM];
__device__ float g_mid[(size_t)SEQ * FFNDIM];
__device__ float g_wqkvt[(size_t)QKVN * DIM];
__device__ float g_bqkv[QKVN];
__device__ float g_wot[DIM * DIM];
__device__ float g_wf1t[(size_t)FFNDIM * DIM];
__device__ float g_wf2t[(size_t)DIM * FFNDIM];

// ---------------- helpers ----------------
__device__ __forceinline__ float f2tf_f(float x) {
    uint32_t u;
    asm("cvt.rna.tf32.f32 %0, %1;" : "=r"(u) : "f"(x));
    return __uint_as_float(u);
}

__device__ __forceinline__ void mma_tf32(float* d, const uint32_t* a,
                                         const uint32_t* b) {
    asm volatile(
        "mma.sync.aligned.m16n8k8.row.col.f32.tf32.tf32.f32 "
        "{%0,%1,%2,%3}, {%4,%5,%6,%7}, {%8,%9}, {%0,%1,%2,%3};"
        : "+f"(d[0]), "+f"(d[1]), "+f"(d[2]), "+f"(d[3])
        : "r"(a[0]), "r"(a[1]), "r"(a[2]), "r"(a[3]),
          "r"(b[0]), "r"(b[1]));
}

__device__ __forceinline__ uint32_t smem_u32(const void* p) {
    uint32_t a;
    asm("{ .reg .u64 t; cvta.to.shared.u64 t, %1; cvt.u32.u64 %0, t; }" : "=r"(a) : "l"(p));
    return a;
}
#define CP_ASYNC16(s, g) \
    asm volatile("cp.async.cg.shared.global [%0], [%1], 16;" :: "r"(s), "l"(g))
#define CP_COMMIT() asm volatile("cp.async.commit_group;" ::: "memory")
#define CP_WAIT1() asm volatile("cp.async.wait_group 1;" ::: "memory")

// ---------------- transpose (rounds to tf32): out[C,R] = tf32(in[R,C]^T) ----------------
__global__ void transpose_k(const float* __restrict__ in, float* __restrict__ out,
                            int R, int C, int ldo) {
    __shared__ float t[32][33];
    int c = blockIdx.x * 32 + threadIdx.x;
    int r = blockIdx.y * 32 + threadIdx.y;
#pragma unroll
    for (int j = 0; j < 32; j += 8)
        t[threadIdx.y + j][threadIdx.x] = in[(size_t)(r + j) * C + c];
    __syncthreads();
    int oc = blockIdx.y * 32 + threadIdx.x;
    int orr = blockIdx.x * 32 + threadIdx.y;
#pragma unroll
    for (int j = 0; j < 32; j += 8)
        out[(size_t)(orr + j) * ldo + oc] = f2tf_f(t[threadIdx.x][threadIdx.y + j]);
}

// ---------------- fused QKV bias: [bq | 0 | bv] ----------------
__global__ void qkvbias_k(const float* __restrict__ bq, const float* __restrict__ bv,
                          float* __restrict__ out) {
    int i = blockIdx.x * 256 + threadIdx.x;
    float v = 0.f;
    if (i < DIM) v = bq[i];
    else if (i >= 2 * DIM) v = bv[i - 2 * DIM];
    out[i] = v;
}

// ---------------- LayerNorm (output rounded to tf32) ----------------
__global__ void ln_kernel(const float* __restrict__ x, const float* __restrict__ g,
                          const float* __restrict__ b, float* __restrict__ y) {
    int row = blockIdx.x;
    const float* xr = x + (size_t)row * DIM;
    float v[5];
    float s = 0.f, sq = 0.f;
#pragma unroll
    for (int i = 0; i < 5; i++) {
        v[i] = xr[threadIdx.x + i * 256];
        s += v[i];
        sq += v[i] * v[i];
    }
    __shared__ float red[64];
#pragma unroll
    for (int o = 16; o > 0; o >>= 1) {
        s += __shfl_xor_sync(0xFFFFFFFFu, s, o);
        sq += __shfl_xor_sync(0xFFFFFFFFu, sq, o);
    }
    int w = threadIdx.x >> 5, l = threadIdx.x & 31;
    if (l == 0) { red[w] = s; red[w + 8] = sq; }
    __syncthreads();
    if (threadIdx.x < 32) {
        float ss = (threadIdx.x < 8) ? red[threadIdx.x] : 0.f;
        float qq = (threadIdx.x < 8) ? red[threadIdx.x + 8] : 0.f;
#pragma unroll
        for (int o = 4; o > 0; o >>= 1) {
            ss += __shfl_xor_sync(0xFFFFFFFFu, ss, o);
            qq += __shfl_xor_sync(0xFFFFFFFFu, qq, o);
        }
        if (threadIdx.x == 0) { red[32] = ss; red[33] = qq; }
    }
    __syncthreads();
    float mu  = red[32] * (1.f / DIM);
    float var = red[33] * (1.f / DIM) - mu * mu;
    float inv = rsqrtf(var + 1e-5f);
    float* yr = y + (size_t)row * DIM;
#pragma unroll
    for (int i = 0; i < 5; i++) {
        int c = threadIdx.x + i * 256;
        yr[c] = f2tf_f((v[i] - mu) * inv * g[c] + b[c]);
    }
}

// ---------------- tf32 mma.sync GEMM, cp.async 3-stage ----------------
#define EPI_NONE 0
#define EPI_BIAS 1
#define EPI_GELU 2
#define EPI_BIAS_RES 3

#define BK 32
#define PITCH 36
#define A_FLOATS (128 * PITCH)
#define STAGE_FLOATS (2 * A_FLOATS)
#define GEMM_DSMEM (3 * STAGE_FLOATS * 4)

template <int EPI>
__global__ __launch_bounds__(256, 2) void mma_gemm(
    const float* __restrict__ A, const float* __restrict__ Bt,
    const float* __restrict__ bias, const float* __restrict__ res,
    float* __restrict__ C, int Ntot, int K) {
    extern __shared__ float sm[];
    uint32_t smb = smem_u32(sm);

    int tid = threadIdx.x;
    int wid = tid >> 5, lane = tid & 31;
    int warp_m = wid & 1;
    int warp_n = wid >> 1;
    int g = lane >> 2, c = lane & 3;
    int br = blockIdx.y * 128, bc = blockIdx.x * 128;

    int rowq = tid >> 3;
    int f4 = tid & 7;
    const float* Abase = A + (size_t)br * K + f4 * 4;
    const float* Bbase = Bt + (size_t)bc * K + f4 * 4;

    const int NIT = K / BK;

    float acc[4][4][4];
#pragma unroll
    for (int i = 0; i < 4; i++)
#pragma unroll
        for (int j = 0; j < 4; j++)
#pragma unroll
            for (int u = 0; u < 4; u++) acc[i][j][u] = 0.f;

#define ISSUE_STAGE(st)                                                      \
    do {                                                                     \
        int _k0 = (st) * BK;                                                 \
        uint32_t _sa = smb + ((st) % 3) * (STAGE_FLOATS * 4);                \
        uint32_t _sb = _sa + A_FLOATS * 4;                                   \
        _Pragma("unroll")                                                    \
        for (int _p = 0; _p < 4; _p++) {                                     \
            int _row = _p * 32 + rowq;                                       \
            uint32_t _so = (uint32_t)(_row * PITCH + f4 * 4) * 4;            \
            CP_ASYNC16(_sa + _so, Abase + (size_t)_row * K + _k0);           \
            CP_ASYNC16(_sb + _so, Bbase + (size_t)_row * K + _k0);           \
        }                                                                    \
    } while (0)

    ISSUE_STAGE(0);
    CP_COMMIT();
    ISSUE_STAGE(1);
    CP_COMMIT();

    for (int it = 0; it < NIT; it++) {
        CP_WAIT1();
        __syncthreads();
        if (it + 2 < NIT) ISSUE_STAGE(it + 2);
        CP_COMMIT();

        const uint32_t* As = (const uint32_t*)(sm + (it % 3) * STAGE_FLOATS);
        const uint32_t* Bs = As + A_FLOATS;
#pragma unroll
        for (int ks = 0; ks < 4; ks++) {
            int k0 = ks * 8;
            uint32_t af[4][4], bf[4][2];
#pragma unroll
            for (int mt = 0; mt < 4; mt++) {
                int rm = warp_m * 64 + mt * 16 + g;
                af[mt][0] = As[rm * PITCH + k0 + c];
                af[mt][1] = As[(rm + 8) * PITCH + k0 + c];
                af[mt][2] = As[rm * PITCH + k0 + c + 4];
                af[mt][3] = As[(rm + 8) * PITCH + k0 + c + 4];
            }
#pragma unroll
            for (int nt = 0; nt < 4; nt++) {
                int rn = warp_n * 32 + nt * 8 + g;
                bf[nt][0] = Bs[rn * PITCH + k0 + c];
                bf[nt][1] = Bs[rn * PITCH + k0 + c + 4];
            }
#pragma unroll
            for (int mt = 0; mt < 4; mt++)
#pragma unroll
                for (int nt = 0; nt < 4; nt++)
                    mma_tf32(acc[mt][nt], af[mt], bf[nt]);
        }
        __syncthreads();
    }

#pragma unroll
    for (int mt = 0; mt < 4; mt++) {
#pragma unroll
        for (int nt = 0; nt < 4; nt++) {
            int col = bc + warp_n * 32 + nt * 8 + c * 2;
#pragma unroll
            for (int half = 0; half < 2; half++) {
                int row = br + warp_m * 64 + mt * 16 + g + half * 8;
                float x0 = acc[mt][nt][half * 2 + 0];
                float x1 = acc[mt][nt][half * 2 + 1];
                if (EPI == EPI_BIAS || EPI == EPI_GELU || EPI == EPI_BIAS_RES) {
                    x0 += bias[col];
                    x1 += bias[col + 1];
                }
                if (EPI == EPI_GELU) {
                    x0 = f2tf_f(0.5f * x0 * (1.f + erff(x0 * 0.70710678118654752f)));
                    x1 = f2tf_f(0.5f * x1 * (1.f + erff(x1 * 0.70710678118654752f)));
                }
                if (EPI == EPI_BIAS_RES) {
                    float2 r2 = *(const float2*)(res + (size_t)row * Ntot + col);
                    x0 += r2.x;
                    x1 += r2.y;
                }
                *(float2*)(C + (size_t)row * Ntot + col) = make_float2(x0, x1);
            }
        }
    }
}

// ---------------- tensor-core block-diagonal attention ----------------
// CTA = 32 queries x (head, segment). smem: scoresT[512][33], Qs[32][68], KV chunk.
#define SP 33
#define QPITCH 68
#define VPITCH 132
#define ASM_Q (512 * SP)
#define ASM_KV (ASM_Q + 32 * QPITCH)
#define ATTN_SMEM_FLOATS (ASM_KV + 128 * QPITCH)   // K chunk 128x68 (> V 64x132)

__global__ __launch_bounds__(256) void attn_kernel(
    const float* __restrict__ Q, const float* __restrict__ Kg,
    const float* __restrict__ V, float* __restrict__ O, int ldq) {
    extern __shared__ float sm[];
    float* scoresT = sm;
    float* Qs = sm + ASM_Q;
    float* KV = sm + ASM_KV;
    uint32_t* scoresT_u = (uint32_t*)scoresT;
    const uint32_t* Qs_u = (const uint32_t*)Qs;
    const uint32_t* KV_u = (const uint32_t*)KV;

    int tid = threadIdx.x;
    int wid = tid >> 5, lane = tid & 31;
    int g = lane >> 2, c = lane & 3;
    int qt = blockIdx.x;   // 0..15
    int hh = blockIdx.y;
    int sg = blockIdx.z;
    int qbase = sg * SEGLEN + qt * 32;
    int kbase = sg * SEGLEN;
    int colbase = hh * HD;

    // load Q tile 32x64 (scaled, tf32) into Qs pitch 68
#pragma unroll
    for (int i = 0; i < 2; i++) {
        int idx = tid + i * 256;       // 0..511 float4 slots
        int r = idx >> 4, f4 = idx & 15;
        float4 qv = *(const float4*)(Q + (size_t)(qbase + r) * ldq + colbase + f4 * 4);
        float* dst = &Qs[r * QPITCH + f4 * 4];
        dst[0] = f2tf_f(qv.x * 0.125f);
        dst[1] = f2tf_f(qv.y * 0.125f);
        dst[2] = f2tf_f(qv.z * 0.125f);
        dst[3] = f2tf_f(qv.w * 0.125f);
    }

    // ---- Phase A: S = Q @ K^T via mma, chunks of 128 keys ----
    for (int kc = 0; kc < 4; kc++) {
        __syncthreads();
        // load K chunk [128 keys][64 d] K-major, tf32
#pragma unroll
        for (int i = 0; i < 8; i++) {
            int idx = tid + i * 256;   // 2048 float4
            int r = idx >> 4, f4 = idx & 15;
            float4 kv = *(const float4*)(Kg + (size_t)(kbase + kc * 128 + r) * ldq + colbase + f4 * 4);
            float* dst = &KV[r * QPITCH + f4 * 4];
            dst[0] = f2tf_f(kv.x);
            dst[1] = f2tf_f(kv.y);
            dst[2] = f2tf_f(kv.z);
            dst[3] = f2tf_f(kv.w);
        }
        __syncthreads();

        float accS[2][2][4];
#pragma unroll
        for (int mt = 0; mt < 2; mt++)
#pragma unroll
            for (int nt = 0; nt < 2; nt++)
#pragma unroll
                for (int u = 0; u < 4; u++) accS[mt][nt][u] = 0.f;

#pragma unroll
        for (int ks = 0; ks < 8; ks++) {
            int k0 = ks * 8;
            uint32_t qa[2][4];
#pragma unroll
            for (int mt = 0; mt < 2; mt++) {
                int rm = mt * 16 + g;
                qa[mt][0] = Qs_u[rm * QPITCH + k0 + c];
                qa[mt][1] = Qs_u[(rm + 8) * QPITCH + k0 + c];
                qa[mt][2] = Qs_u[rm * QPITCH + k0 + c + 4];
                qa[mt][3] = Qs_u[(rm + 8) * QPITCH + k0 + c + 4];
            }
#pragma unroll
            for (int nt = 0; nt < 2; nt++) {
                int rk = wid * 16 + nt * 8 + g;   // local key row
                uint32_t kb[2];
                kb[0] = KV_u[rk * QPITCH + k0 + c];
                kb[1] = KV_u[rk * QPITCH + k0 + c + 4];
#pragma unroll
                for (int mt = 0; mt < 2; mt++)
                    mma_tf32(accS[mt][nt], qa[mt], kb);
            }
        }
        // scatter S into scoresT[key][q]
#pragma unroll
        for (int mt = 0; mt < 2; mt++)
#pragma unroll
            for (int nt = 0; nt < 2; nt++) {
                int keyg = kc * 128 + wid * 16 + nt * 8 + 2 * c;
                int q0 = mt * 16 + g;
                scoresT[keyg * SP + q0]           = accS[mt][nt][0];
                scoresT[(keyg + 1) * SP + q0]     = accS[mt][nt][1];
                scoresT[keyg * SP + q0 + 8]       = accS[mt][nt][2];
                scoresT[(keyg + 1) * SP + q0 + 8] = accS[mt][nt][3];
            }
    }
    __syncthreads();

    // ---- softmax (warp w handles queries w, w+8, w+16, w+24), tf32-rounded probs ----
    {
        int w = wid, l = lane;
        for (int qi = 0; qi < 4; qi++) {
            int q = w + qi * 8;
            float vals[16];
            float m = -1e30f;
#pragma unroll
            for (int s = 0; s < 16; s++) {
                vals[s] = scoresT[(l + s * 32) * SP + q];
                m = fmaxf(m, vals[s]);
            }
#pragma unroll
            for (int o = 16; o > 0; o >>= 1) m = fmaxf(m, __shfl_xor_sync(0xFFFFFFFFu, m, o));
            float sum = 0.f;
#pragma unroll
            for (int s = 0; s < 16; s++) {
                float e = __expf(vals[s] - m);
                vals[s] = e;
                sum += e;
            }
#pragma unroll
            for (int o = 16; o > 0; o >>= 1) sum += __shfl_xor_sync(0xFFFFFFFFu, sum, o);
            float r = 1.f / sum;
#pragma unroll
            for (int s = 0; s < 16; s++)
                scoresT[(l + s * 32) * SP + q] = f2tf_f(vals[s] * r);
        }
    }

    // ---- Phase C: O = P @ V via mma ----
    int mhalf = wid & 1;      // q half: rows 16*mhalf..
    int dq = wid >> 1;        // d quad: cols 16*dq..
    int q0 = mhalf * 16, d0 = dq * 16;
    float accO[2][4];
#pragma unroll
    for (int nt = 0; nt < 2; nt++)
#pragma unroll
        for (int u = 0; u < 4; u++) accO[nt][u] = 0.f;

    for (int kc = 0; kc < 4; kc++) {
        __syncthreads();
        // load V chunk transposed: Vt[d(64)][key(128)] pitch 132, tf32
#pragma unroll
        for (int i = 0; i < 8; i++) {
            int idx = tid + i * 256;
            int r = idx >> 4, f4 = idx & 15;   // key row r, d group f4
            float4 vv = *(const float4*)(V + (size_t)(kbase + kc * 128 + r) * ldq + colbase + f4 * 4);
            int d = f4 * 4;
            KV[d * VPITCH + r]       = f2tf_f(vv.x);
            KV[(d + 1) * VPITCH + r] = f2tf_f(vv.y);
            KV[(d + 2) * VPITCH + r] = f2tf_f(vv.z);
            KV[(d + 3) * VPITCH + r] = f2tf_f(vv.w);
        }
        __syncthreads();

#pragma unroll
        for (int ks = 0; ks < 16; ks++) {
            int k0 = ks * 8;                   // local key
            int keyg = kc * 128 + k0;
            uint32_t pa[4];
            pa[0] = scoresT_u[(keyg + c) * SP + q0 + g];
            pa[1] = scoresT_u[(keyg + c) * SP + q0 + 8 + g];
            pa[2] = scoresT_u[(keyg + c + 4) * SP + q0 + g];
            pa[3] = scoresT_u[(keyg + c + 4) * SP + q0 + 8 + g];
#pragma unroll
            for (int nt = 0; nt < 2; nt++) {
                uint32_t vb[2];
                int dn = d0 + nt * 8 + g;
                vb[0] = KV_u[dn * VPITCH + k0 + c];
                vb[1] = KV_u[dn * VPITCH + k0 + c + 4];
                mma_tf32(accO[nt], pa, vb);
            }
        }
    }

    // write O (tf32-rounded, feeds O-projection)
#pragma unroll
    for (int nt = 0; nt < 2; nt++) {
        int dcol = colbase + d0 + nt * 8 + 2 * c;
        float* r0 = &O[(size_t)(qbase + q0 + g) * DIM + dcol];
        float* r1 = &O[(size_t)(qbase + q0 + 8 + g) * DIM + dcol];
        *(float2*)r0 = make_float2(f2tf_f(accO[nt][0]), f2tf_f(accO[nt][1]));
        *(float2*)r1 = make_float2(f2tf_f(accO[nt][2]), f2tf_f(accO[nt][3]));
    }
}

// ---------------- launch ----------------
extern "C" void kernel_launch(void* const* d_in, const int* in_sizes, int n_in,
                              void* d_out, int out_size) {
    const float* hidden = (const float*)d_in[0];
    const float* Wq = (const float*)d_in[2];
    const float* bq = (const float*)d_in[3];
    const float* Wk = (const float*)d_in[4];
    const float* Wv = (const float*)d_in[5];
    const float* bv = (const float*)d_in[6];
    const float* Wo = (const float*)d_in[7];
    const float* bo = (const float*)d_in[8];
    const float* g1 = (const float*)d_in[9];
    const float* b1 = (const float*)d_in[10];
    const float* Wf1 = (const float*)d_in[11];
    const float* bf1 = (const float*)d_in[12];
    const float* Wf2 = (const float*)d_in[13];
    const float* bf2 = (const float*)d_in[14];
    const float* g2 = (const float*)d_in[15];
    const float* b2 = (const float*)d_in[16];
    float* out = (float*)d_out;

    float *xln, *qkv, *attn, *h, *yln, *mid;
    float *wqkvt, *bqkv, *wot, *wf1t, *wf2t;
    cudaGetSymbolAddress((void**)&xln, g_xln);
    cudaGetSymbolAddress((void**)&qkv, g_qkv);
    cudaGetSymbolAddress((void**)&attn, g_attn);
    cudaGetSymbolAddress((void**)&h, g_h);
    cudaGetSymbolAddress((void**)&yln, g_yln);
    cudaGetSymbolAddress((void**)&mid, g_mid);
    cudaGetSymbolAddress((void**)&wqkvt, g_wqkvt);
    cudaGetSymbolAddress((void**)&bqkv, g_bqkv);
    cudaGetSymbolAddress((void**)&wot, g_wot);
    cudaGetSymbolAddress((void**)&wf1t, g_wf1t);
    cudaGetSymbolAddress((void**)&wf2t, g_wf2t);

    const int ATTN_SMEM = ATTN_SMEM_FLOATS * 4;
    cudaFuncSetAttribute(attn_kernel, cudaFuncAttributeMaxDynamicSharedMemorySize, ATTN_SMEM);
    cudaFuncSetAttribute(mma_gemm<EPI_NONE>, cudaFuncAttributeMaxDynamicSharedMemorySize, GEMM_DSMEM);
    cudaFuncSetAttribute(mma_gemm<EPI_BIAS>, cudaFuncAttributeMaxDynamicSharedMemorySize, GEMM_DSMEM);
    cudaFuncSetAttribute(mma_gemm<EPI_GELU>, cudaFuncAttributeMaxDynamicSharedMemorySize, GEMM_DSMEM);
    cudaFuncSetAttribute(mma_gemm<EPI_BIAS_RES>, cudaFuncAttributeMaxDynamicSharedMemorySize, GEMM_DSMEM);

    dim3 tb(32, 8);
    transpose_k<<<dim3(DIM / 32, DIM / 32), tb>>>(Wq, wqkvt, DIM, DIM, DIM);
    transpose_k<<<dim3(DIM / 32, DIM / 32), tb>>>(Wk, wqkvt + (size_t)DIM * DIM, DIM, DIM, DIM);
    transpose_k<<<dim3(DIM / 32, DIM / 32), tb>>>(Wv, wqkvt + (size_t)2 * DIM * DIM, DIM, DIM, DIM);
    transpose_k<<<dim3(DIM / 32, DIM / 32), tb>>>(Wo, wot, DIM, DIM, DIM);
    transpose_k<<<dim3(FFNDIM / 32, DIM / 32), tb>>>(Wf1, wf1t, DIM, FFNDIM, DIM);
    transpose_k<<<dim3(DIM / 32, FFNDIM / 32), tb>>>(Wf2, wf2t, FFNDIM, DIM, FFNDIM);
    qkvbias_k<<<QKVN / 256, 256>>>(bq, bv, bqkv);

    dim3 gQKV(QKVN / 128, SEQ / 128);
    dim3 gD(DIM / 128, SEQ / 128);
    dim3 gF(FFNDIM / 128, SEQ / 128);

    // LN1
    ln_kernel<<<SEQ, 256>>>(hidden, g1, b1, xln);
    // fused QKV GEMM -> [4096, 3840]
    mma_gemm<EPI_BIAS><<<gQKV, 256, GEMM_DSMEM>>>(xln, wqkvt, bqkv, nullptr, qkv, QKVN, DIM);
    // tensor-core attention (block-diagonal, 512-token segments)
    attn_kernel<<<dim3(16, NH, 8), 256, ATTN_SMEM>>>(qkv, qkv + DIM, qkv + 2 * DIM, attn, QKVN);
    // O proj + residual
    mma_gemm<EPI_BIAS_RES><<<gD, 256, GEMM_DSMEM>>>(attn, wot, bo, hidden, h, DIM, DIM);
    // LN2
    ln_kernel<<<SEQ, 256>>>(h, g2, b2, yln);
    // FFN
    mma_gemm<EPI_GELU><<<gF, 256, GEMM_DSMEM>>>(yln, wf1t, bf1, nullptr, mid, FFNDIM, DIM);
    mma_gemm<EPI_BIAS_RES><<<gD, 256, GEMM_DSMEM>>>(mid, wf2t, bf2, h, out, DIM, FFNDIM);
}

// round 9
// speedup vs baseline: 2.3534x; 1.4777x over previous
#include <cuda_runtime.h>
#include <cuda_fp16.h>
#include <math.h>
#include <stdint.h>

#define SEQ 4096
#define DIM 1280
#define NH 20
#define HD 64
#define FFNDIM 5120
#define SEGLEN 512
#define QKVN 3840

// ---------------- scratch (no allocations allowed) ----------------
__device__ __half g_xln[SEQ * DIM];
__device__ __half g_qkv[(size_t)SEQ * QKVN];
__device__ __half g_attnh[SEQ * DIM];
__device__ float  g_h[SEQ * DIM];
__device__ __half g_yln[SEQ * DIM];
__device__ __half g_mid[(size_t)SEQ * FFNDIM];
__device__ __half g_wqkvt[(size_t)QKVN * DIM];
__device__ float  g_bqkv[QKVN];
__device__ __half g_wot[DIM * DIM];
__device__ __half g_wf1t[(size_t)FFNDIM * DIM];
__device__ __half g_wf2t[(size_t)DIM * FFNDIM];

// ---------------- helpers ----------------
__device__ __forceinline__ float f2tf_f(float x) {
    uint32_t u;
    asm("cvt.rna.tf32.f32 %0, %1;" : "=r"(u) : "f"(x));
    return __uint_as_float(u);
}

__device__ __forceinline__ void mma_f16(float* d, const uint32_t* a,
                                        const uint32_t* b) {
    asm volatile(
        "mma.sync.aligned.m16n8k16.row.col.f32.f16.f16.f32 "
        "{%0,%1,%2,%3}, {%4,%5,%6,%7}, {%8,%9}, {%0,%1,%2,%3};"
        : "+f"(d[0]), "+f"(d[1]), "+f"(d[2]), "+f"(d[3])
        : "r"(a[0]), "r"(a[1]), "r"(a[2]), "r"(a[3]),
          "r"(b[0]), "r"(b[1]));
}

__device__ __forceinline__ void mma_tf32(float* d, const uint32_t* a,
                                         const uint32_t* b) {
    asm volatile(
        "mma.sync.aligned.m16n8k8.row.col.f32.tf32.tf32.f32 "
        "{%0,%1,%2,%3}, {%4,%5,%6,%7}, {%8,%9}, {%0,%1,%2,%3};"
        : "+f"(d[0]), "+f"(d[1]), "+f"(d[2]), "+f"(d[3])
        : "r"(a[0]), "r"(a[1]), "r"(a[2]), "r"(a[3]),
          "r"(b[0]), "r"(b[1]));
}

__device__ __forceinline__ uint32_t smem_u32(const void* p) {
    uint32_t a;
    asm("{ .reg .u64 t; cvta.to.shared.u64 t, %1; cvt.u32.u64 %0, t; }" : "=r"(a) : "l"(p));
    return a;
}
#define CP_ASYNC16(s, g) \
    asm volatile("cp.async.cg.shared.global [%0], [%1], 16;" :: "r"(s), "l"(g))
#define CP_COMMIT() asm volatile("cp.async.commit_group;" ::: "memory")
#define CP_WAIT1() asm volatile("cp.async.wait_group 1;" ::: "memory")

// ---------------- transpose to half: out[C,R] = h(in[R,C]^T) ----------------
__global__ void transpose_k(const float* __restrict__ in, __half* __restrict__ out,
                            int R, int C, int ldo) {
    __shared__ float t[32][33];
    int c = blockIdx.x * 32 + threadIdx.x;
    int r = blockIdx.y * 32 + threadIdx.y;
#pragma unroll
    for (int j = 0; j < 32; j += 8)
        t[threadIdx.y + j][threadIdx.x] = in[(size_t)(r + j) * C + c];
    __syncthreads();
    int oc = blockIdx.y * 32 + threadIdx.x;
    int orr = blockIdx.x * 32 + threadIdx.y;
#pragma unroll
    for (int j = 0; j < 32; j += 8)
        out[(size_t)(orr + j) * ldo + oc] = __float2half(t[threadIdx.x][threadIdx.y + j]);
}

// ---------------- fused QKV bias: [bq | 0 | bv] ----------------
__global__ void qkvbias_k(const float* __restrict__ bq, const float* __restrict__ bv,
                          float* __restrict__ out) {
    int i = blockIdx.x * 256 + threadIdx.x;
    float v = 0.f;
    if (i < DIM) v = bq[i];
    else if (i >= 2 * DIM) v = bv[i - 2 * DIM];
    out[i] = v;
}

// ---------------- LayerNorm (half output) ----------------
__global__ void ln_kernel(const float* __restrict__ x, const float* __restrict__ g,
                          const float* __restrict__ b, __half* __restrict__ y) {
    int row = blockIdx.x;
    const float* xr = x + (size_t)row * DIM;
    float v[5];
    float s = 0.f, sq = 0.f;
#pragma unroll
    for (int i = 0; i < 5; i++) {
        v[i] = xr[threadIdx.x + i * 256];
        s += v[i];
        sq += v[i] * v[i];
    }
    __shared__ float red[64];
#pragma unroll
    for (int o = 16; o > 0; o >>= 1) {
        s += __shfl_xor_sync(0xFFFFFFFFu, s, o);
        sq += __shfl_xor_sync(0xFFFFFFFFu, sq, o);
    }
    int w = threadIdx.x >> 5, l = threadIdx.x & 31;
    if (l == 0) { red[w] = s; red[w + 8] = sq; }
    __syncthreads();
    if (threadIdx.x < 32) {
        float ss = (threadIdx.x < 8) ? red[threadIdx.x] : 0.f;
        float qq = (threadIdx.x < 8) ? red[threadIdx.x + 8] : 0.f;
#pragma unroll
        for (int o = 4; o > 0; o >>= 1) {
            ss += __shfl_xor_sync(0xFFFFFFFFu, ss, o);
            qq += __shfl_xor_sync(0xFFFFFFFFu, qq, o);
        }
        if (threadIdx.x == 0) { red[32] = ss; red[33] = qq; }
    }
    __syncthreads();
    float mu  = red[32] * (1.f / DIM);
    float var = red[33] * (1.f / DIM) - mu * mu;
    float inv = rsqrtf(var + 1e-5f);
    __half* yr = y + (size_t)row * DIM;
#pragma unroll
    for (int i = 0; i < 5; i++) {
        int c = threadIdx.x + i * 256;
        yr[c] = __float2half((v[i] - mu) * inv * g[c] + b[c]);
    }
}

// ---------------- fp16 mma.sync GEMM, cp.async 3-stage ----------------
// C[M,Ntot] = A[M,K] @ Bt[N,K]^T ; A,Bt half, accum fp32.
#define EPI_NONE 0
#define EPI_BIAS 1
#define EPI_GELU 2
#define EPI_BIAS_RES 3

#define BK 32                         // halves per K chunk
#define PWH 40                        // pitch in halves (word pitch 20)
#define A_HALVES (128 * PWH)          // 5120 halves = 10240 B
#define A_WORDS (A_HALVES / 2)        // 2560
#define STAGE_BYTES (2 * A_HALVES * 2)  // 20480
#define GEMM_DSMEM (3 * STAGE_BYTES)    // 61440

template <int EPI, int OUTH>
__global__ __launch_bounds__(256, 2) void mma_gemm(
    const __half* __restrict__ A, const __half* __restrict__ Bt,
    const float* __restrict__ bias, const float* __restrict__ res,
    void* __restrict__ Cv, int Ntot, int K) {
    extern __shared__ __align__(16) char smc[];
    uint32_t smb = smem_u32(smc);

    int tid = threadIdx.x;
    int wid = tid >> 5, lane = tid & 31;
    int warp_m = wid & 1;
    int warp_n = wid >> 1;
    int g = lane >> 2, c = lane & 3;
    int br = blockIdx.y * 128, bc = blockIdx.x * 128;

    const __half* Abase = A + (size_t)br * K;
    const __half* Bbase = Bt + (size_t)bc * K;

    const int NIT = K / BK;

    float acc[4][4][4];
#pragma unroll
    for (int i = 0; i < 4; i++)
#pragma unroll
        for (int j = 0; j < 4; j++)
#pragma unroll
            for (int u = 0; u < 4; u++) acc[i][j][u] = 0.f;

    // stage issue: 512 x 16B chunks per tile (row = s>>2, slot f4 = s&3)
#define ISSUE_STAGE(st)                                                       \
    do {                                                                      \
        int _k0 = (st) * BK;                                                  \
        uint32_t _sa = smb + ((st) % 3) * STAGE_BYTES;                        \
        uint32_t _sb = _sa + A_HALVES * 2;                                    \
        _Pragma("unroll")                                                     \
        for (int _i = 0; _i < 2; _i++) {                                      \
            int _s = tid + _i * 256;                                          \
            int _row = _s >> 2, _f4 = _s & 3;                                 \
            uint32_t _so = (uint32_t)(_row * (PWH * 2) + _f4 * 16);           \
            CP_ASYNC16(_sa + _so, Abase + (size_t)_row * K + _k0 + _f4 * 8);  \
            CP_ASYNC16(_sb + _so, Bbase + (size_t)_row * K + _k0 + _f4 * 8);  \
        }                                                                     \
    } while (0)

    ISSUE_STAGE(0);
    CP_COMMIT();
    ISSUE_STAGE(1);
    CP_COMMIT();

    for (int it = 0; it < NIT; it++) {
        CP_WAIT1();
        __syncthreads();
        if (it + 2 < NIT) ISSUE_STAGE(it + 2);
        CP_COMMIT();

        const uint32_t* As = (const uint32_t*)(smc + (it % 3) * STAGE_BYTES);
        const uint32_t* Bs = As + A_WORDS;
#pragma unroll
        for (int kk = 0; kk < 2; kk++) {     // two k16 steps per BK=32
            int kw = kk * 8;                 // word offset
            uint32_t af[4][4], bf[4][2];
#pragma unroll
            for (int mt = 0; mt < 4; mt++) {
                int rm = warp_m * 64 + mt * 16 + g;
                af[mt][0] = As[rm * 20 + kw + c];
                af[mt][1] = As[(rm + 8) * 20 + kw + c];
                af[mt][2] = As[rm * 20 + kw + c + 4];
                af[mt][3] = As[(rm + 8) * 20 + kw + c + 4];
            }
#pragma unroll
            for (int nt = 0; nt < 4; nt++) {
                int rn = warp_n * 32 + nt * 8 + g;
                bf[nt][0] = Bs[rn * 20 + kw + c];
                bf[nt][1] = Bs[rn * 20 + kw + c + 4];
            }
#pragma unroll
            for (int mt = 0; mt < 4; mt++)
#pragma unroll
                for (int nt = 0; nt < 4; nt++)
                    mma_f16(acc[mt][nt], af[mt], bf[nt]);
        }
        __syncthreads();
    }

    // epilogue
#pragma unroll
    for (int mt = 0; mt < 4; mt++) {
#pragma unroll
        for (int nt = 0; nt < 4; nt++) {
            int col = bc + warp_n * 32 + nt * 8 + c * 2;
#pragma unroll
            for (int half = 0; half < 2; half++) {
                int row = br + warp_m * 64 + mt * 16 + g + half * 8;
                float x0 = acc[mt][nt][half * 2 + 0];
                float x1 = acc[mt][nt][half * 2 + 1];
                if (EPI == EPI_BIAS || EPI == EPI_GELU || EPI == EPI_BIAS_RES) {
                    x0 += bias[col];
                    x1 += bias[col + 1];
                }
                if (EPI == EPI_GELU) {
                    x0 = 0.5f * x0 * (1.f + erff(x0 * 0.70710678118654752f));
                    x1 = 0.5f * x1 * (1.f + erff(x1 * 0.70710678118654752f));
                }
                if (EPI == EPI_BIAS_RES) {
                    float2 r2 = *(const float2*)(res + (size_t)row * Ntot + col);
                    x0 += r2.x;
                    x1 += r2.y;
                }
                if (OUTH) {
                    __half2* Ch = (__half2*)Cv;
                    Ch[((size_t)row * Ntot + col) >> 1] = __floats2half2_rn(x0, x1);
                } else {
                    float* Cf = (float*)Cv;
                    *(float2*)(Cf + (size_t)row * Ntot + col) = make_float2(x0, x1);
                }
            }
        }
    }
}

// ---------------- tensor-core block-diagonal attention (half in/out) ----------------
#define SP 33
#define QPITCH 68
#define VPITCH 132
#define ASM_Q (512 * SP)
#define ASM_KV (ASM_Q + 32 * QPITCH)
#define ATTN_SMEM_FLOATS (ASM_KV + 128 * QPITCH)

__global__ __launch_bounds__(256) void attn_kernel(
    const __half* __restrict__ Q, const __half* __restrict__ Kg,
    const __half* __restrict__ V, __half* __restrict__ O, int ldq) {
    extern __shared__ float sm[];
    float* scoresT = sm;
    float* Qs = sm + ASM_Q;
    float* KV = sm + ASM_KV;
    uint32_t* scoresT_u = (uint32_t*)scoresT;
    const uint32_t* Qs_u = (const uint32_t*)Qs;
    const uint32_t* KV_u = (const uint32_t*)KV;

    int tid = threadIdx.x;
    int wid = tid >> 5, lane = tid & 31;
    int g = lane >> 2, c = lane & 3;
    int qt = blockIdx.x;
    int hh = blockIdx.y;
    int sg = blockIdx.z;
    int qbase = sg * SEGLEN + qt * 32;
    int kbase = sg * SEGLEN;
    int colbase = hh * HD;

    // load Q tile 32x64 half -> fp32 smem (scaled); fp16 values are tf32-exact
    {
        int r = tid >> 3, f8 = tid & 7;    // 256 slots of 8 halves
        uint4 raw = *(const uint4*)(Q + (size_t)(qbase + r) * ldq + colbase + f8 * 8);
        const __half2* hp = (const __half2*)&raw;
        float* dst = &Qs[r * QPITCH + f8 * 8];
#pragma unroll
        for (int j = 0; j < 4; j++) {
            float2 f = __half22float2(hp[j]);
            dst[2 * j] = f.x * 0.125f;
            dst[2 * j + 1] = f.y * 0.125f;
        }
    }

    // ---- Phase A: S = Q @ K^T (tf32 mma), chunks of 128 keys ----
    for (int kc = 0; kc < 4; kc++) {
        __syncthreads();
#pragma unroll
        for (int i = 0; i < 4; i++) {
            int s = tid + i * 256;         // 1024 slots of 8 halves
            int r = s >> 3, f8 = s & 7;
            uint4 raw = *(const uint4*)(Kg + (size_t)(kbase + kc * 128 + r) * ldq + colbase + f8 * 8);
            const __half2* hp = (const __half2*)&raw;
            float* dst = &KV[r * QPITCH + f8 * 8];
#pragma unroll
            for (int j = 0; j < 4; j++) {
                float2 f = __half22float2(hp[j]);
                dst[2 * j] = f.x;
                dst[2 * j + 1] = f.y;
            }
        }
        __syncthreads();

        float accS[2][2][4];
#pragma unroll
        for (int mt = 0; mt < 2; mt++)
#pragma unroll
            for (int nt = 0; nt < 2; nt++)
#pragma unroll
                for (int u = 0; u < 4; u++) accS[mt][nt][u] = 0.f;

#pragma unroll
        for (int ks = 0; ks < 8; ks++) {
            int k0 = ks * 8;
            uint32_t qa[2][4];
#pragma unroll
            for (int mt = 0; mt < 2; mt++) {
                int rm = mt * 16 + g;
                qa[mt][0] = Qs_u[rm * QPITCH + k0 + c];
                qa[mt][1] = Qs_u[(rm + 8) * QPITCH + k0 + c];
                qa[mt][2] = Qs_u[rm * QPITCH + k0 + c + 4];
                qa[mt][3] = Qs_u[(rm + 8) * QPITCH + k0 + c + 4];
            }
#pragma unroll
            for (int nt = 0; nt < 2; nt++) {
                int rk = wid * 16 + nt * 8 + g;
                uint32_t kb[2];
                kb[0] = KV_u[rk * QPITCH + k0 + c];
                kb[1] = KV_u[rk * QPITCH + k0 + c + 4];
#pragma unroll
                for (int mt = 0; mt < 2; mt++)
                    mma_tf32(accS[mt][nt], qa[mt], kb);
            }
        }
#pragma unroll
        for (int mt = 0; mt < 2; mt++)
#pragma unroll
            for (int nt = 0; nt < 2; nt++) {
                int keyg = kc * 128 + wid * 16 + nt * 8 + 2 * c;
                int q0 = mt * 16 + g;
                scoresT[keyg * SP + q0]           = accS[mt][nt][0];
                scoresT[(keyg + 1) * SP + q0]     = accS[mt][nt][1];
                scoresT[keyg * SP + q0 + 8]       = accS[mt][nt][2];
                scoresT[(keyg + 1) * SP + q0 + 8] = accS[mt][nt][3];
            }
    }
    __syncthreads();

    // ---- softmax (tf32-rounded probs) ----
    {
        int w = wid, l = lane;
        for (int qi = 0; qi < 4; qi++) {
            int q = w + qi * 8;
            float vals[16];
            float m = -1e30f;
#pragma unroll
            for (int s = 0; s < 16; s++) {
                vals[s] = scoresT[(l + s * 32) * SP + q];
                m = fmaxf(m, vals[s]);
            }
#pragma unroll
            for (int o = 16; o > 0; o >>= 1) m = fmaxf(m, __shfl_xor_sync(0xFFFFFFFFu, m, o));
            float sum = 0.f;
#pragma unroll
            for (int s = 0; s < 16; s++) {
                float e = __expf(vals[s] - m);
                vals[s] = e;
                sum += e;
            }
#pragma unroll
            for (int o = 16; o > 0; o >>= 1) sum += __shfl_xor_sync(0xFFFFFFFFu, sum, o);
            float r = 1.f / sum;
#pragma unroll
            for (int s = 0; s < 16; s++)
                scoresT[(l + s * 32) * SP + q] = f2tf_f(vals[s] * r);
        }
    }

    // ---- Phase C: O = P @ V (tf32 mma) ----
    int mhalf = wid & 1;
    int dq = wid >> 1;
    int q0 = mhalf * 16, d0 = dq * 16;
    float accO[2][4];
#pragma unroll
    for (int nt = 0; nt < 2; nt++)
#pragma unroll
        for (int u = 0; u < 4; u++) accO[nt][u] = 0.f;

    for (int kc = 0; kc < 4; kc++) {
        __syncthreads();
#pragma unroll
        for (int i = 0; i < 4; i++) {
            int s = tid + i * 256;
            int r = s >> 3, f8 = s & 7;
            uint4 raw = *(const uint4*)(V + (size_t)(kbase + kc * 128 + r) * ldq + colbase + f8 * 8);
            const __half2* hp = (const __half2*)&raw;
            int d = f8 * 8;
#pragma unroll
            for (int j = 0; j < 4; j++) {
                float2 f = __half22float2(hp[j]);
                KV[(d + 2 * j) * VPITCH + r]     = f.x;
                KV[(d + 2 * j + 1) * VPITCH + r] = f.y;
            }
        }
        __syncthreads();

#pragma unroll
        for (int ks = 0; ks < 16; ks++) {
            int k0 = ks * 8;
            int keyg = kc * 128 + k0;
            uint32_t pa[4];
            pa[0] = scoresT_u[(keyg + c) * SP + q0 + g];
            pa[1] = scoresT_u[(keyg + c) * SP + q0 + 8 + g];
            pa[2] = scoresT_u[(keyg + c + 4) * SP + q0 + g];
            pa[3] = scoresT_u[(keyg + c + 4) * SP + q0 + 8 + g];
#pragma unroll
            for (int nt = 0; nt < 2; nt++) {
                uint32_t vb[2];
                int dn = d0 + nt * 8 + g;
                vb[0] = KV_u[dn * VPITCH + k0 + c];
                vb[1] = KV_u[dn * VPITCH + k0 + c + 4];
                mma_tf32(accO[nt], pa, vb);
            }
        }
    }

    // write O as half (feeds O-projection GEMM)
#pragma unroll
    for (int nt = 0; nt < 2; nt++) {
        int dcol = colbase + d0 + nt * 8 + 2 * c;
        __half2* r0 = (__half2*)&O[(size_t)(qbase + q0 + g) * DIM + dcol];
        __half2* r1 = (__half2*)&O[(size_t)(qbase + q0 + 8 + g) * DIM + dcol];
        *r0 = __floats2half2_rn(accO[nt][0], accO[nt][1]);
        *r1 = __floats2half2_rn(accO[nt][2], accO[nt][3]);
    }
}

// ---------------- launch ----------------
extern "C" void kernel_launch(void* const* d_in, const int* in_sizes, int n_in,
                              void* d_out, int out_size) {
    const float* hidden = (const float*)d_in[0];
    const float* Wq = (const float*)d_in[2];
    const float* bq = (const float*)d_in[3];
    const float* Wk = (const float*)d_in[4];
    const float* Wv = (const float*)d_in[5];
    const float* bv = (const float*)d_in[6];
    const float* Wo = (const float*)d_in[7];
    const float* bo = (const float*)d_in[8];
    const float* g1 = (const float*)d_in[9];
    const float* b1 = (const float*)d_in[10];
    const float* Wf1 = (const float*)d_in[11];
    const float* bf1 = (const float*)d_in[12];
    const float* Wf2 = (const float*)d_in[13];
    const float* bf2 = (const float*)d_in[14];
    const float* g2 = (const float*)d_in[15];
    const float* b2 = (const float*)d_in[16];
    float* out = (float*)d_out;

    __half *xln, *qkv, *attnh, *yln, *mid;
    __half *wqkvt, *wot, *wf1t, *wf2t;
    float *h, *bqkv;
    cudaGetSymbolAddress((void**)&xln, g_xln);
    cudaGetSymbolAddress((void**)&qkv, g_qkv);
    cudaGetSymbolAddress((void**)&attnh, g_attnh);
    cudaGetSymbolAddress((void**)&h, g_h);
    cudaGetSymbolAddress((void**)&yln, g_yln);
    cudaGetSymbolAddress((void**)&mid, g_mid);
    cudaGetSymbolAddress((void**)&wqkvt, g_wqkvt);
    cudaGetSymbolAddress((void**)&bqkv, g_bqkv);
    cudaGetSymbolAddress((void**)&wot, g_wot);
    cudaGetSymbolAddress((void**)&wf1t, g_wf1t);
    cudaGetSymbolAddress((void**)&wf2t, g_wf2t);

    const int ATTN_SMEM = ATTN_SMEM_FLOATS * 4;
    cudaFuncSetAttribute(attn_kernel, cudaFuncAttributeMaxDynamicSharedMemorySize, ATTN_SMEM);
    cudaFuncSetAttribute(mma_gemm<EPI_BIAS, 1>, cudaFuncAttributeMaxDynamicSharedMemorySize, GEMM_DSMEM);
    cudaFuncSetAttribute(mma_gemm<EPI_GELU, 1>, cudaFuncAttributeMaxDynamicSharedMemorySize, GEMM_DSMEM);
    cudaFuncSetAttribute(mma_gemm<EPI_BIAS_RES, 0>, cudaFuncAttributeMaxDynamicSharedMemorySize, GEMM_DSMEM);

    dim3 tb(32, 8);
    transpose_k<<<dim3(DIM / 32, DIM / 32), tb>>>(Wq, wqkvt, DIM, DIM, DIM);
    transpose_k<<<dim3(DIM / 32, DIM / 32), tb>>>(Wk, wqkvt + (size_t)DIM * DIM, DIM, DIM, DIM);
    transpose_k<<<dim3(DIM / 32, DIM / 32), tb>>>(Wv, wqkvt + (size_t)2 * DIM * DIM, DIM, DIM, DIM);
    transpose_k<<<dim3(DIM / 32, DIM / 32), tb>>>(Wo, wot, DIM, DIM, DIM);
    transpose_k<<<dim3(FFNDIM / 32, DIM / 32), tb>>>(Wf1, wf1t, DIM, FFNDIM, DIM);
    transpose_k<<<dim3(DIM / 32, FFNDIM / 32), tb>>>(Wf2, wf2t, FFNDIM, DIM, FFNDIM);
    qkvbias_k<<<QKVN / 256, 256>>>(bq, bv, bqkv);

    dim3 gQKV(QKVN / 128, SEQ / 128);
    dim3 gD(DIM / 128, SEQ / 128);
    dim3 gF(FFNDIM / 128, SEQ / 128);

    // LN1 (half out)
    ln_kernel<<<SEQ, 256>>>(hidden, g1, b1, xln);
    // fused QKV GEMM -> half [4096, 3840]
    mma_gemm<EPI_BIAS, 1><<<gQKV, 256, GEMM_DSMEM>>>(xln, wqkvt, bqkv, nullptr, qkv, QKVN, DIM);
    // attention (block-diagonal), half in/out
    attn_kernel<<<dim3(16, NH, 8), 256, ATTN_SMEM>>>(qkv, qkv + DIM, qkv + 2 * DIM, attnh, QKVN);
    // O proj + residual (fp32 out)
    mma_gemm<EPI_BIAS_RES, 0><<<gD, 256, GEMM_DSMEM>>>(attnh, wot, bo, hidden, h, DIM, DIM);
    // LN2 (half out)
    ln_kernel<<<SEQ, 256>>>(h, g2, b2, yln);
    // FFN
    mma_gemm<EPI_GELU, 1><<<gF, 256, GEMM_DSMEM>>>(yln, wf1t, bf1, nullptr, mid, FFNDIM, DIM);
    mma_gemm<EPI_BIAS_RES, 0><<<gD, 256, GEMM_DSMEM>>>(mid, wf2t, bf2, h, out, DIM, FFNDIM);
}

// round 10
// speedup vs baseline: 2.4670x; 1.0483x over previous
#include <cuda_runtime.h>
#include <cuda_fp16.h>
#include <math.h>
#include <stdint.h>

#define SEQ 4096
#define DIM 1280
#define NH 20
#define HD 64
#define FFNDIM 5120
#define SEGLEN 512
#define QKVN 3840

// ---------------- scratch (no allocations allowed) ----------------
__device__ __half g_xln[SEQ * DIM];
__device__ __half g_qkv[(size_t)SEQ * QKVN];
__device__ __half g_attnh[SEQ * DIM];
__device__ float  g_h[SEQ * DIM];
__device__ __half g_yln[SEQ * DIM];
__device__ __half g_mid[(size_t)SEQ * FFNDIM];
__device__ __half g_wqkvt[(size_t)QKVN * DIM];
__device__ float  g_bqkv[QKVN];
__device__ __half g_wot[DIM * DIM];
__device__ __half g_wf1t[(size_t)FFNDIM * DIM];
__device__ __half g_wf2t[(size_t)DIM * FFNDIM];

// ---------------- helpers ----------------
__device__ __forceinline__ float f2tf_f(float x) {
    uint32_t u;
    asm("cvt.rna.tf32.f32 %0, %1;" : "=r"(u) : "f"(x));
    return __uint_as_float(u);
}

__device__ __forceinline__ void mma_f16(float* d, const uint32_t* a,
                                        const uint32_t* b) {
    asm volatile(
        "mma.sync.aligned.m16n8k16.row.col.f32.f16.f16.f32 "
        "{%0,%1,%2,%3}, {%4,%5,%6,%7}, {%8,%9}, {%0,%1,%2,%3};"
        : "+f"(d[0]), "+f"(d[1]), "+f"(d[2]), "+f"(d[3])
        : "r"(a[0]), "r"(a[1]), "r"(a[2]), "r"(a[3]),
          "r"(b[0]), "r"(b[1]));
}

__device__ __forceinline__ void mma_tf32(float* d, const uint32_t* a,
                                         const uint32_t* b) {
    asm volatile(
        "mma.sync.aligned.m16n8k8.row.col.f32.tf32.tf32.f32 "
        "{%0,%1,%2,%3}, {%4,%5,%6,%7}, {%8,%9}, {%0,%1,%2,%3};"
        : "+f"(d[0]), "+f"(d[1]), "+f"(d[2]), "+f"(d[3])
        : "r"(a[0]), "r"(a[1]), "r"(a[2]), "r"(a[3]),
          "r"(b[0]), "r"(b[1]));
}

__device__ __forceinline__ uint32_t smem_u32(const void* p) {
    uint32_t a;
    asm("{ .reg .u64 t; cvta.to.shared.u64 t, %1; cvt.u32.u64 %0, t; }" : "=r"(a) : "l"(p));
    return a;
}
#define CP_ASYNC16(s, g) \
    asm volatile("cp.async.cg.shared.global [%0], [%1], 16;" :: "r"(s), "l"(g))
#define CP_COMMIT() asm volatile("cp.async.commit_group;" ::: "memory")
#define CP_WAIT2() asm volatile("cp.async.wait_group 2;" ::: "memory")

#define LDSM_X4(r0, r1, r2, r3, addr)                                        \
    asm volatile("ldmatrix.sync.aligned.m8n8.x4.shared.b16 {%0,%1,%2,%3}, [%4];" \
        : "=r"(r0), "=r"(r1), "=r"(r2), "=r"(r3) : "r"(addr))
#define LDSM_X2(r0, r1, addr)                                                \
    asm volatile("ldmatrix.sync.aligned.m8n8.x2.shared.b16 {%0,%1}, [%2];"   \
        : "=r"(r0), "=r"(r1) : "r"(addr))

// ---------------- transpose to half ----------------
__global__ void transpose_k(const float* __restrict__ in, __half* __restrict__ out,
                            int R, int C, int ldo) {
    __shared__ float t[32][33];
    int c = blockIdx.x * 32 + threadIdx.x;
    int r = blockIdx.y * 32 + threadIdx.y;
#pragma unroll
    for (int j = 0; j < 32; j += 8)
        t[threadIdx.y + j][threadIdx.x] = in[(size_t)(r + j) * C + c];
    __syncthreads();
    int oc = blockIdx.y * 32 + threadIdx.x;
    int orr = blockIdx.x * 32 + threadIdx.y;
#pragma unroll
    for (int j = 0; j < 32; j += 8)
        out[(size_t)(orr + j) * ldo + oc] = __float2half(t[threadIdx.x][threadIdx.y + j]);
}

// ---------------- fused QKV bias ----------------
__global__ void qkvbias_k(const float* __restrict__ bq, const float* __restrict__ bv,
                          float* __restrict__ out) {
    int i = blockIdx.x * 256 + threadIdx.x;
    float v = 0.f;
    if (i < DIM) v = bq[i];
    else if (i >= 2 * DIM) v = bv[i - 2 * DIM];
    out[i] = v;
}

// ---------------- LayerNorm (half output) ----------------
__global__ void ln_kernel(const float* __restrict__ x, const float* __restrict__ g,
                          const float* __restrict__ b, __half* __restrict__ y) {
    int row = blockIdx.x;
    const float* xr = x + (size_t)row * DIM;
    float v[5];
    float s = 0.f, sq = 0.f;
#pragma unroll
    for (int i = 0; i < 5; i++) {
        v[i] = xr[threadIdx.x + i * 256];
        s += v[i];
        sq += v[i] * v[i];
    }
    __shared__ float red[64];
#pragma unroll
    for (int o = 16; o > 0; o >>= 1) {
        s += __shfl_xor_sync(0xFFFFFFFFu, s, o);
        sq += __shfl_xor_sync(0xFFFFFFFFu, sq, o);
    }
    int w = threadIdx.x >> 5, l = threadIdx.x & 31;
    if (l == 0) { red[w] = s; red[w + 8] = sq; }
    __syncthreads();
    if (threadIdx.x < 32) {
        float ss = (threadIdx.x < 8) ? red[threadIdx.x] : 0.f;
        float qq = (threadIdx.x < 8) ? red[threadIdx.x + 8] : 0.f;
#pragma unroll
        for (int o = 4; o > 0; o >>= 1) {
            ss += __shfl_xor_sync(0xFFFFFFFFu, ss, o);
            qq += __shfl_xor_sync(0xFFFFFFFFu, qq, o);
        }
        if (threadIdx.x == 0) { red[32] = ss; red[33] = qq; }
    }
    __syncthreads();
    float mu  = red[32] * (1.f / DIM);
    float var = red[33] * (1.f / DIM) - mu * mu;
    float inv = rsqrtf(var + 1e-5f);
    __half* yr = y + (size_t)row * DIM;
#pragma unroll
    for (int i = 0; i < 5; i++) {
        int c = threadIdx.x + i * 256;
        yr[c] = __float2half((v[i] - mu) * inv * g[c] + b[c]);
    }
}

// ---------------- fp16 mma GEMM, cp.async 4-stage + ldmatrix ----------------
#define EPI_NONE 0
#define EPI_BIAS 1
#define EPI_GELU 2
#define EPI_BIAS_RES 3

#define BK 32                           // halves per K chunk
#define PWH 40                          // pitch in halves (80 B/row)
#define A_HALVES (128 * PWH)            // 5120 halves
#define A_BYTES (A_HALVES * 2)          // 10240
#define STAGE_BYTES (2 * A_BYTES)       // 20480
#define GEMM_DSMEM (4 * STAGE_BYTES)    // 81920

template <int EPI, int OUTH>
__global__ __launch_bounds__(256, 2) void mma_gemm(
    const __half* __restrict__ A, const __half* __restrict__ Bt,
    const float* __restrict__ bias, const float* __restrict__ res,
    void* __restrict__ Cv, int Ntot, int K) {
    extern __shared__ __align__(16) char smc[];
    uint32_t smb = smem_u32(smc);

    int tid = threadIdx.x;
    int wid = tid >> 5, lane = tid & 31;
    int warp_m = wid & 1;
    int warp_n = wid >> 1;
    int g = lane >> 2, c = lane & 3;
    int br = blockIdx.y * 128, bc = blockIdx.x * 128;

    const __half* Abase = A + (size_t)br * K;
    const __half* Bbase = Bt + (size_t)bc * K;

    const int NIT = K / BK;

    // per-thread ldmatrix base offsets (bytes, within stage)
    uint32_t a_off = (uint32_t)(warp_m * 64 + (lane & 15)) * (PWH * 2) + ((lane >> 4) << 4);
    uint32_t b_off = A_BYTES + (uint32_t)(warp_n * 32 + (lane & 7)) * (PWH * 2) + (((lane >> 3) & 1) << 4);

    float acc[4][4][4];
#pragma unroll
    for (int i = 0; i < 4; i++)
#pragma unroll
        for (int j = 0; j < 4; j++)
#pragma unroll
            for (int u = 0; u < 4; u++) acc[i][j][u] = 0.f;

#define ISSUE_STAGE(st)                                                       \
    do {                                                                      \
        int _k0 = (st) * BK;                                                  \
        uint32_t _sa = smb + ((st) & 3) * STAGE_BYTES;                        \
        uint32_t _sb = _sa + A_BYTES;                                         \
        _Pragma("unroll")                                                     \
        for (int _i = 0; _i < 2; _i++) {                                      \
            int _s = tid + _i * 256;                                          \
            int _row = _s >> 2, _f4 = _s & 3;                                 \
            uint32_t _so = (uint32_t)(_row * (PWH * 2) + _f4 * 16);           \
            CP_ASYNC16(_sa + _so, Abase + (size_t)_row * K + _k0 + _f4 * 8);  \
            CP_ASYNC16(_sb + _so, Bbase + (size_t)_row * K + _k0 + _f4 * 8);  \
        }                                                                     \
    } while (0)

    ISSUE_STAGE(0);
    CP_COMMIT();
    ISSUE_STAGE(1);
    CP_COMMIT();
    ISSUE_STAGE(2);
    CP_COMMIT();

    for (int it = 0; it < NIT; it++) {
        CP_WAIT2();
        __syncthreads();
        if (it + 3 < NIT) ISSUE_STAGE(it + 3);
        CP_COMMIT();

        uint32_t sbase = smb + (it & 3) * STAGE_BYTES;
        uint32_t abase = sbase + a_off;
        uint32_t bbase = sbase + b_off;
#pragma unroll
        for (int kk = 0; kk < 2; kk++) {
            uint32_t koff = kk * 32;
            uint32_t af[4][4], bf[4][2];
#pragma unroll
            for (int mt = 0; mt < 4; mt++)
                LDSM_X4(af[mt][0], af[mt][1], af[mt][2], af[mt][3],
                        abase + (uint32_t)mt * 16 * (PWH * 2) + koff);
#pragma unroll
            for (int nt = 0; nt < 4; nt++)
                LDSM_X2(bf[nt][0], bf[nt][1],
                        bbase + (uint32_t)nt * 8 * (PWH * 2) + koff);
#pragma unroll
            for (int mt = 0; mt < 4; mt++)
#pragma unroll
                for (int nt = 0; nt < 4; nt++)
                    mma_f16(acc[mt][nt], af[mt], bf[nt]);
        }
        __syncthreads();
    }

    // epilogue
#pragma unroll
    for (int mt = 0; mt < 4; mt++) {
#pragma unroll
        for (int nt = 0; nt < 4; nt++) {
            int col = bc + warp_n * 32 + nt * 8 + c * 2;
#pragma unroll
            for (int half = 0; half < 2; half++) {
                int row = br + warp_m * 64 + mt * 16 + g + half * 8;
                float x0 = acc[mt][nt][half * 2 + 0];
                float x1 = acc[mt][nt][half * 2 + 1];
                if (EPI == EPI_BIAS || EPI == EPI_GELU || EPI == EPI_BIAS_RES) {
                    x0 += bias[col];
                    x1 += bias[col + 1];
                }
                if (EPI == EPI_GELU) {
                    x0 = 0.5f * x0 * (1.f + erff(x0 * 0.70710678118654752f));
                    x1 = 0.5f * x1 * (1.f + erff(x1 * 0.70710678118654752f));
                }
                if (EPI == EPI_BIAS_RES) {
                    float2 r2 = *(const float2*)(res + (size_t)row * Ntot + col);
                    x0 += r2.x;
                    x1 += r2.y;
                }
                if (OUTH) {
                    __half2* Ch = (__half2*)Cv;
                    Ch[((size_t)row * Ntot + col) >> 1] = __floats2half2_rn(x0, x1);
                } else {
                    float* Cf = (float*)Cv;
                    *(float2*)(Cf + (size_t)row * Ntot + col) = make_float2(x0, x1);
                }
            }
        }
    }
}

// ---------------- tensor-core block-diagonal attention (half in/out) ----------------
#define SP 33
#define QPITCH 68
#define VPITCH 132
#define ASM_Q (512 * SP)
#define ASM_KV (ASM_Q + 32 * QPITCH)
#define ATTN_SMEM_FLOATS (ASM_KV + 128 * QPITCH)

__global__ __launch_bounds__(256) void attn_kernel(
    const __half* __restrict__ Q, const __half* __restrict__ Kg,
    const __half* __restrict__ V, __half* __restrict__ O, int ldq) {
    extern __shared__ float sm[];
    float* scoresT = sm;
    float* Qs = sm + ASM_Q;
    float* KV = sm + ASM_KV;
    uint32_t* scoresT_u = (uint32_t*)scoresT;
    const uint32_t* Qs_u = (const uint32_t*)Qs;
    const uint32_t* KV_u = (const uint32_t*)KV;

    int tid = threadIdx.x;
    int wid = tid >> 5, lane = tid & 31;
    int g = lane >> 2, c = lane & 3;
    int qt = blockIdx.x;
    int hh = blockIdx.y;
    int sg = blockIdx.z;
    int qbase = sg * SEGLEN + qt * 32;
    int kbase = sg * SEGLEN;
    int colbase = hh * HD;

    {
        int r = tid >> 3, f8 = tid & 7;
        uint4 raw = *(const uint4*)(Q + (size_t)(qbase + r) * ldq + colbase + f8 * 8);
        const __half2* hp = (const __half2*)&raw;
        float* dst = &Qs[r * QPITCH + f8 * 8];
#pragma unroll
        for (int j = 0; j < 4; j++) {
            float2 f = __half22float2(hp[j]);
            dst[2 * j] = f.x * 0.125f;
            dst[2 * j + 1] = f.y * 0.125f;
        }
    }

    // ---- Phase A: S = Q @ K^T ----
    for (int kc = 0; kc < 4; kc++) {
        __syncthreads();
#pragma unroll
        for (int i = 0; i < 4; i++) {
            int s = tid + i * 256;
            int r = s >> 3, f8 = s & 7;
            uint4 raw = *(const uint4*)(Kg + (size_t)(kbase + kc * 128 + r) * ldq + colbase + f8 * 8);
            const __half2* hp = (const __half2*)&raw;
            float* dst = &KV[r * QPITCH + f8 * 8];
#pragma unroll
            for (int j = 0; j < 4; j++) {
                float2 f = __half22float2(hp[j]);
                dst[2 * j] = f.x;
                dst[2 * j + 1] = f.y;
            }
        }
        __syncthreads();

        float accS[2][2][4];
#pragma unroll
        for (int mt = 0; mt < 2; mt++)
#pragma unroll
            for (int nt = 0; nt < 2; nt++)
#pragma unroll
                for (int u = 0; u < 4; u++) accS[mt][nt][u] = 0.f;

#pragma unroll
        for (int ks = 0; ks < 8; ks++) {
            int k0 = ks * 8;
            uint32_t qa[2][4];
#pragma unroll
            for (int mt = 0; mt < 2; mt++) {
                int rm = mt * 16 + g;
                qa[mt][0] = Qs_u[rm * QPITCH + k0 + c];
                qa[mt][1] = Qs_u[(rm + 8) * QPITCH + k0 + c];
                qa[mt][2] = Qs_u[rm * QPITCH + k0 + c + 4];
                qa[mt][3] = Qs_u[(rm + 8) * QPITCH + k0 + c + 4];
            }
#pragma unroll
            for (int nt = 0; nt < 2; nt++) {
                int rk = wid * 16 + nt * 8 + g;
                uint32_t kb[2];
                kb[0] = KV_u[rk * QPITCH + k0 + c];
                kb[1] = KV_u[rk * QPITCH + k0 + c + 4];
#pragma unroll
                for (int mt = 0; mt < 2; mt++)
                    mma_tf32(accS[mt][nt], qa[mt], kb);
            }
        }
#pragma unroll
        for (int mt = 0; mt < 2; mt++)
#pragma unroll
            for (int nt = 0; nt < 2; nt++) {
                int keyg = kc * 128 + wid * 16 + nt * 8 + 2 * c;
                int q0 = mt * 16 + g;
                scoresT[keyg * SP + q0]           = accS[mt][nt][0];
                scoresT[(keyg + 1) * SP + q0]     = accS[mt][nt][1];
                scoresT[keyg * SP + q0 + 8]       = accS[mt][nt][2];
                scoresT[(keyg + 1) * SP + q0 + 8] = accS[mt][nt][3];
            }
    }
    __syncthreads();

    // ---- softmax ----
    {
        int w = wid, l = lane;
        for (int qi = 0; qi < 4; qi++) {
            int q = w + qi * 8;
            float vals[16];
            float m = -1e30f;
#pragma unroll
            for (int s = 0; s < 16; s++) {
                vals[s] = scoresT[(l + s * 32) * SP + q];
                m = fmaxf(m, vals[s]);
            }
#pragma unroll
            for (int o = 16; o > 0; o >>= 1) m = fmaxf(m, __shfl_xor_sync(0xFFFFFFFFu, m, o));
            float sum = 0.f;
#pragma unroll
            for (int s = 0; s < 16; s++) {
                float e = __expf(vals[s] - m);
                vals[s] = e;
                sum += e;
            }
#pragma unroll
            for (int o = 16; o > 0; o >>= 1) sum += __shfl_xor_sync(0xFFFFFFFFu, sum, o);
            float r = 1.f / sum;
#pragma unroll
            for (int s = 0; s < 16; s++)
                scoresT[(l + s * 32) * SP + q] = f2tf_f(vals[s] * r);
        }
    }

    // ---- Phase C: O = P @ V ----
    int mhalf = wid & 1;
    int dq = wid >> 1;
    int q0 = mhalf * 16, d0 = dq * 16;
    float accO[2][4];
#pragma unroll
    for (int nt = 0; nt < 2; nt++)
#pragma unroll
        for (int u = 0; u < 4; u++) accO[nt][u] = 0.f;

    for (int kc = 0; kc < 4; kc++) {
        __syncthreads();
#pragma unroll
        for (int i = 0; i < 4; i++) {
            int s = tid + i * 256;
            int r = s >> 3, f8 = s & 7;
            uint4 raw = *(const uint4*)(V + (size_t)(kbase + kc * 128 + r) * ldq + colbase + f8 * 8);
            const __half2* hp = (const __half2*)&raw;
            int d = f8 * 8;
#pragma unroll
            for (int j = 0; j < 4; j++) {
                float2 f = __half22float2(hp[j]);
                KV[(d + 2 * j) * VPITCH + r]     = f.x;
                KV[(d + 2 * j + 1) * VPITCH + r] = f.y;
            }
        }
        __syncthreads();

#pragma unroll
        for (int ks = 0; ks < 16; ks++) {
            int k0 = ks * 8;
            int keyg = kc * 128 + k0;
            uint32_t pa[4];
            pa[0] = scoresT_u[(keyg + c) * SP + q0 + g];
            pa[1] = scoresT_u[(keyg + c) * SP + q0 + 8 + g];
            pa[2] = scoresT_u[(keyg + c + 4) * SP + q0 + g];
            pa[3] = scoresT_u[(keyg + c + 4) * SP + q0 + 8 + g];
#pragma unroll
            for (int nt = 0; nt < 2; nt++) {
                uint32_t vb[2];
                int dn = d0 + nt * 8 + g;
                vb[0] = KV_u[dn * VPITCH + k0 + c];
                vb[1] = KV_u[dn * VPITCH + k0 + c + 4];
                mma_tf32(accO[nt], pa, vb);
            }
        }
    }

#pragma unroll
    for (int nt = 0; nt < 2; nt++) {
        int dcol = colbase + d0 + nt * 8 + 2 * c;
        __half2* r0 = (__half2*)&O[(size_t)(qbase + q0 + g) * DIM + dcol];
        __half2* r1 = (__half2*)&O[(size_t)(qbase + q0 + 8 + g) * DIM + dcol];
        *r0 = __floats2half2_rn(accO[nt][0], accO[nt][1]);
        *r1 = __floats2half2_rn(accO[nt][2], accO[nt][3]);
    }
}

// ---------------- launch ----------------
extern "C" void kernel_launch(void* const* d_in, const int* in_sizes, int n_in,
                              void* d_out, int out_size) {
    const float* hidden = (const float*)d_in[0];
    const float* Wq = (const float*)d_in[2];
    const float* bq = (const float*)d_in[3];
    const float* Wk = (const float*)d_in[4];
    const float* Wv = (const float*)d_in[5];
    const float* bv = (const float*)d_in[6];
    const float* Wo = (const float*)d_in[7];
    const float* bo = (const float*)d_in[8];
    const float* g1 = (const float*)d_in[9];
    const float* b1 = (const float*)d_in[10];
    const float* Wf1 = (const float*)d_in[11];
    const float* bf1 = (const float*)d_in[12];
    const float* Wf2 = (const float*)d_in[13];
    const float* bf2 = (const float*)d_in[14];
    const float* g2 = (const float*)d_in[15];
    const float* b2 = (const float*)d_in[16];
    float* out = (float*)d_out;

    __half *xln, *qkv, *attnh, *yln, *mid;
    __half *wqkvt, *wot, *wf1t, *wf2t;
    float *h, *bqkv;
    cudaGetSymbolAddress((void**)&xln, g_xln);
    cudaGetSymbolAddress((void**)&qkv, g_qkv);
    cudaGetSymbolAddress((void**)&attnh, g_attnh);
    cudaGetSymbolAddress((void**)&h, g_h);
    cudaGetSymbolAddress((void**)&yln, g_yln);
    cudaGetSymbolAddress((void**)&mid, g_mid);
    cudaGetSymbolAddress((void**)&wqkvt, g_wqkvt);
    cudaGetSymbolAddress((void**)&bqkv, g_bqkv);
    cudaGetSymbolAddress((void**)&wot, g_wot);
    cudaGetSymbolAddress((void**)&wf1t, g_wf1t);
    cudaGetSymbolAddress((void**)&wf2t, g_wf2t);

    const int ATTN_SMEM = ATTN_SMEM_FLOATS * 4;
    cudaFuncSetAttribute(attn_kernel, cudaFuncAttributeMaxDynamicSharedMemorySize, ATTN_SMEM);
    cudaFuncSetAttribute(mma_gemm<EPI_BIAS, 1>, cudaFuncAttributeMaxDynamicSharedMemorySize, GEMM_DSMEM);
    cudaFuncSetAttribute(mma_gemm<EPI_GELU, 1>, cudaFuncAttributeMaxDynamicSharedMemorySize, GEMM_DSMEM);
    cudaFuncSetAttribute(mma_gemm<EPI_BIAS_RES, 0>, cudaFuncAttributeMaxDynamicSharedMemorySize, GEMM_DSMEM);

    dim3 tb(32, 8);
    transpose_k<<<dim3(DIM / 32, DIM / 32), tb>>>(Wq, wqkvt, DIM, DIM, DIM);
    transpose_k<<<dim3(DIM / 32, DIM / 32), tb>>>(Wk, wqkvt + (size_t)DIM * DIM, DIM, DIM, DIM);
    transpose_k<<<dim3(DIM / 32, DIM / 32), tb>>>(Wv, wqkvt + (size_t)2 * DIM * DIM, DIM, DIM, DIM);
    transpose_k<<<dim3(DIM / 32, DIM / 32), tb>>>(Wo, wot, DIM, DIM, DIM);
    transpose_k<<<dim3(FFNDIM / 32, DIM / 32), tb>>>(Wf1, wf1t, DIM, FFNDIM, DIM);
    transpose_k<<<dim3(DIM / 32, FFNDIM / 32), tb>>>(Wf2, wf2t, FFNDIM, DIM, FFNDIM);
    qkvbias_k<<<QKVN / 256, 256>>>(bq, bv, bqkv);

    dim3 gQKV(QKVN / 128, SEQ / 128);
    dim3 gD(DIM / 128, SEQ / 128);
    dim3 gF(FFNDIM / 128, SEQ / 128);

    // LN1 (half out)
    ln_kernel<<<SEQ, 256>>>(hidden, g1, b1, xln);
    // fused QKV GEMM -> half [4096, 3840]
    mma_gemm<EPI_BIAS, 1><<<gQKV, 256, GEMM_DSMEM>>>(xln, wqkvt, bqkv, nullptr, qkv, QKVN, DIM);
    // attention (block-diagonal), half in/out
    attn_kernel<<<dim3(16, NH, 8), 256, ATTN_SMEM>>>(qkv, qkv + DIM, qkv + 2 * DIM, attnh, QKVN);
    // O proj + residual (fp32 out)
    mma_gemm<EPI_BIAS_RES, 0><<<gD, 256, GEMM_DSMEM>>>(attnh, wot, bo, hidden, h, DIM, DIM);
    // LN2 (half out)
    ln_kernel<<<SEQ, 256>>>(h, g2, b2, yln);
    // FFN
    mma_gemm<EPI_GELU, 1><<<gF, 256, GEMM_DSMEM>>>(yln, wf1t, bf1, nullptr, mid, FFNDIM, DIM);
    mma_gemm<EPI_BIAS_RES, 0><<<gD, 256, GEMM_DSMEM>>>(mid, wf2t, bf2, h, out, DIM, FFNDIM);
}